// round 7
// baseline (speedup 1.0000x reference)
#include <cuda_runtime.h>
#include <cuda_fp16.h>
#include <cstdint>

// ---------------------------------------------------------------------------
// Problem constants (B=4, H=W=64, DIM=512, 8 heads, SR=2)
// ---------------------------------------------------------------------------
#define BATCH   4
#define HH      64
#define WW      64
#define NN      (HH * WW)        // 4096
#define DIMC    512
#define NHEAD   8
#define HD      (DIMC / NHEAD)   // 64
#define SRR     2
#define HP      (HH / SRR)       // 32
#define WP      (WW / SRR)       // 32
#define NP      (HP * WP)        // 1024
#define KSR     (DIMC * SRR * SRR) // 2048

// ---------------------------------------------------------------------------
// Scratch (device globals)
// ---------------------------------------------------------------------------
__device__ __half g_xh  [(size_t)BATCH * NN * DIMC];     // x fp16
__device__ float  g_Xsr [(size_t)BATCH * NP * DIMC];     // conv out fp32 (LN input)
__device__ __half g_Xnh [(size_t)BATCH * NP * DIMC];     // LN out
__device__ __half g_KVh [(size_t)BATCH * NP * 2 * DIMC];
__device__ __half g_Qh  [(size_t)BATCH * NN * DIMC];     // pre-scaled Q
__device__ __half g_Oh  [(size_t)BATCH * NN * DIMC];
__device__ __half g_Wsrh[(size_t)DIMC * KSR];            // reordered (o, q*512+c)
__device__ __half g_Wkvh[(size_t)2 * DIMC * DIMC];
__device__ __half g_Wqh [(size_t)DIMC * DIMC];
__device__ __half g_Wph [(size_t)DIMC * DIMC];

__device__ __forceinline__ __half* pick_h(int id) {
    switch (id) {
        case 1: return g_xh;
        case 2: return g_Xnh;
        case 3: return g_KVh;
        case 4: return g_Qh;
        case 5: return g_Oh;
        case 6: return g_Wsrh;
        case 7: return g_Wkvh;
        case 8: return g_Wqh;
        case 9: return g_Wph;
    }
    return nullptr;
}

// ---------------------------------------------------------------------------
// PTX helpers
// ---------------------------------------------------------------------------
__device__ __forceinline__ uint32_t smem_u32(const void* p) {
    uint32_t a;
    asm("{ .reg .u64 t; cvta.to.shared.u64 t, %1; cvt.u32.u64 %0, t; }"
        : "=r"(a) : "l"(p));
    return a;
}
__device__ __forceinline__ uint32_t h2pack(float a, float b) {
    __half2 h = __floats2half2_rn(a, b);
    return *(uint32_t*)&h;
}
__device__ __forceinline__ void mma16816(float c[4],
                                         uint32_t a0, uint32_t a1,
                                         uint32_t a2, uint32_t a3,
                                         uint32_t b0, uint32_t b1) {
    asm volatile(
        "mma.sync.aligned.m16n8k16.row.col.f32.f16.f16.f32 "
        "{%0,%1,%2,%3}, {%4,%5,%6,%7}, {%8,%9}, {%0,%1,%2,%3};"
        : "+f"(c[0]), "+f"(c[1]), "+f"(c[2]), "+f"(c[3])
        : "r"(a0), "r"(a1), "r"(a2), "r"(a3), "r"(b0), "r"(b1));
}
__device__ __forceinline__ void ldmx4(uint32_t r[4], uint32_t addr) {
    asm volatile(
        "ldmatrix.sync.aligned.m8n8.x4.shared.b16 {%0,%1,%2,%3}, [%4];"
        : "=r"(r[0]), "=r"(r[1]), "=r"(r[2]), "=r"(r[3]) : "r"(addr));
}
__device__ __forceinline__ void ldmx4t(uint32_t r[4], uint32_t addr) {
    asm volatile(
        "ldmatrix.sync.aligned.m8n8.x4.trans.shared.b16 {%0,%1,%2,%3}, [%4];"
        : "=r"(r[0]), "=r"(r[1]), "=r"(r[2]), "=r"(r[3]) : "r"(addr));
}
#define CP_ASYNC16(saddr, gptr) \
    asm volatile("cp.async.cg.shared.global [%0], [%1], 16;" \
        :: "r"(saddr), "l"(gptr))
#define CP_COMMIT() asm volatile("cp.async.commit_group;" ::: "memory")
#define CP_WAIT(N)  asm volatile("cp.async.wait_group %0;" :: "n"(N) : "memory")

// ---------------------------------------------------------------------------
// 0a) x fp32 -> fp16
// ---------------------------------------------------------------------------
__global__ void __launch_bounds__(256) f2h_x(const float* __restrict__ src, int n) {
    int i = (blockIdx.x * blockDim.x + threadIdx.x) * 4;
    if (i >= n) return;
    float4 v = *(const float4*)&src[i];
    *(uint2*)&g_xh[i] = make_uint2(h2pack(v.x, v.y), h2pack(v.z, v.w));
}

// 0b) Wkv + Wq + Wp fp32 -> fp16 (one launch)
#define NKV (2 * DIMC * DIMC)
#define NSQ (DIMC * DIMC)
__global__ void __launch_bounds__(256) f2h_w(const float* __restrict__ wkv,
                                             const float* __restrict__ wq,
                                             const float* __restrict__ wp) {
    int i = (blockIdx.x * blockDim.x + threadIdx.x) * 4;
    const float* src;
    __half* dst;
    if (i < NKV)                { src = wkv + i;              dst = g_Wkvh + i; }
    else if (i < NKV + NSQ)     { src = wq + (i - NKV);       dst = g_Wqh  + (i - NKV); }
    else if (i < NKV + 2 * NSQ) { src = wp + (i - NKV - NSQ); dst = g_Wph  + (i - NKV - NSQ); }
    else return;
    float4 v = *(const float4*)src;
    *(uint2*)dst = make_uint2(h2pack(v.x, v.y), h2pack(v.z, v.w));
}

// 0c) Wsr reorder: g_Wsrh[o][q*512+c] = Wsr[o*2048 + c*4 + q]
__global__ void __launch_bounds__(256) wsr_reorder(const float* __restrict__ wsr) {
    int idx = blockIdx.x * blockDim.x + threadIdx.x;
    if (idx >= DIMC * KSR) return;
    int o = idx >> 11, rest = idx & 2047;
    int q = rest >> 9, c = rest & 511;
    g_Wsrh[idx] = __float2half(wsr[o * 2048 + c * 4 + q]);
}

// ---------------------------------------------------------------------------
// hgemm body: C[M,Nc] = scale*(A[M,K] @ W[Nc,K]^T) + bias
// 128x128 CTA tile, BK=32, 3-stage cp.async, ldmatrix, fp32 accum.
// patchA: A is the (q*512+c)-ordered im2col view of g_xh (M = BATCH*NP rows).
// ---------------------------------------------------------------------------
#define GST 40
#define G_SMEM (3 * 128 * GST * 2 * 2)   // 61440 bytes

__device__ __forceinline__ void hgemm_body(
    char* smem_raw, int Aid, int patchA, int Wid,
    const float* bias, float scale,
    int Cfp16, int Cid, float* Cext,
    int M, int Nc, int K, int m0, int n0)
{
    __half (*As)[128][GST] = (__half (*)[128][GST])smem_raw;
    __half (*Bs)[128][GST] = (__half (*)[128][GST])(smem_raw + 3 * 128 * GST * 2);

    const __half* A = patchA ? g_xh : pick_h(Aid);
    const __half* W = pick_h(Wid);

    const int tid  = threadIdx.x;
    const int wid  = tid >> 5;
    const int lane = tid & 31;
    const int g = lane >> 2, t = lane & 3;
    const int wm = (wid & 3) * 32;
    const int wn = (wid >> 2) * 64;

    // per-thread fill coordinates: two (row, c8) pairs
    const int r0 = tid >> 2;             // 0..63
    const int c8 = (tid & 3) * 8;        // 0,8,16,24
    // patch-mode: base position index for rows r0 and r0+64
    int pb[2];
    if (patchA) {
#pragma unroll
        for (int j = 0; j < 2; j++) {
            int m = m0 + r0 + j * 64;
            int b = m >> 10, np = m & 1023;
            int i = np >> 5, jj = np & 31;
            pb[j] = (b << 12) + i * 128 + jj * 2;
        }
    }

    float acc[2][8][4];
#pragma unroll
    for (int mt = 0; mt < 2; mt++)
#pragma unroll
        for (int nt = 0; nt < 8; nt++)
#pragma unroll
            for (int c = 0; c < 4; c++) acc[mt][nt][c] = 0.f;

    const int nch = K >> 5;

    auto issue = [&](int kc, int buf) {
        const int k0 = kc << 5;
        if (patchA) {
            const int q = k0 >> 9;
            const int offq = ((q >> 1) << 6) + (q & 1);
            const int cc = (k0 & 511) + c8;
#pragma unroll
            for (int j = 0; j < 2; j++) {
                int r = r0 + j * 64;
                CP_ASYNC16(smem_u32(&As[buf][r][c8]),
                           A + (size_t)(pb[j] + offq) * DIMC + cc);
                CP_ASYNC16(smem_u32(&Bs[buf][r][c8]),
                           W + (size_t)(n0 + r) * K + k0 + c8);
            }
        } else {
#pragma unroll
            for (int j = 0; j < 2; j++) {
                int r = r0 + j * 64;
                CP_ASYNC16(smem_u32(&As[buf][r][c8]),
                           A + (size_t)(m0 + r) * K + k0 + c8);
                CP_ASYNC16(smem_u32(&Bs[buf][r][c8]),
                           W + (size_t)(n0 + r) * K + k0 + c8);
            }
        }
        CP_COMMIT();
    };

    issue(0, 0);
    issue(1, 1);

    int buf = 0, bufn = 2;   // bufn = (kc+2) % 3
    for (int kc = 0; kc < nch; kc++) {
        if (kc + 1 < nch) { CP_WAIT(1); } else { CP_WAIT(0); }
        __syncthreads();
        if (kc + 2 < nch) issue(kc + 2, bufn);

#pragma unroll
        for (int ks = 0; ks < 2; ks++) {
            const int kcol = ks * 16;
            uint32_t af[2][4];
#pragma unroll
            for (int mt = 0; mt < 2; mt++)
                ldmx4(af[mt], smem_u32(&As[buf][wm + 16 * mt + (lane & 15)]
                                          [kcol + ((lane >> 4) << 3)]));
            uint32_t bf[4][4];
#pragma unroll
            for (int bp = 0; bp < 4; bp++)
                ldmx4(bf[bp], smem_u32(&Bs[buf][wn + 16 * bp + ((lane >> 4) << 3) + (lane & 7)]
                                          [kcol + ((lane >> 3) & 1) * 8]));
#pragma unroll
            for (int nt = 0; nt < 8; nt++) {
                uint32_t b0 = bf[nt >> 1][(nt & 1) * 2];
                uint32_t b1 = bf[nt >> 1][(nt & 1) * 2 + 1];
                mma16816(acc[0][nt], af[0][0], af[0][1], af[0][2], af[0][3], b0, b1);
                mma16816(acc[1][nt], af[1][0], af[1][1], af[1][2], af[1][3], b0, b1);
            }
        }
        buf = buf == 2 ? 0 : buf + 1;
        bufn = bufn == 2 ? 0 : bufn + 1;
        __syncthreads();
    }

    // epilogue
    __half* Ch = Cfp16 ? pick_h(Cid) : nullptr;
    float*  Cf = Cfp16 ? nullptr : (Cext ? Cext : g_Xsr);
#pragma unroll
    for (int mt = 0; mt < 2; mt++) {
        const int mr = m0 + wm + mt * 16 + g;
#pragma unroll
        for (int nt = 0; nt < 8; nt++) {
            const int n = n0 + wn + nt * 8 + 2 * t;
            float bx = 0.f, by = 0.f;
            if (bias) { bx = bias[n]; by = bias[n + 1]; }
            float v00 = acc[mt][nt][0] * scale + bx;
            float v01 = acc[mt][nt][1] * scale + by;
            float v10 = acc[mt][nt][2] * scale + bx;
            float v11 = acc[mt][nt][3] * scale + by;
            if (Cfp16) {
                *(uint32_t*)&Ch[(size_t)mr * Nc + n]       = h2pack(v00, v01);
                *(uint32_t*)&Ch[(size_t)(mr + 8) * Nc + n] = h2pack(v10, v11);
            } else {
                *(float2*)&Cf[(size_t)mr * Nc + n]       = make_float2(v00, v01);
                *(float2*)&Cf[(size_t)(mr + 8) * Nc + n] = make_float2(v10, v11);
            }
        }
    }
}

// generic GEMM kernel
__global__ void __launch_bounds__(256) hgemm(
    int Aid, int Wid, const float* bias, float scale,
    int Cfp16, int Cid, float* Cext, int M, int Nc, int K)
{
    extern __shared__ char smem_raw[];
    hgemm_body(smem_raw, Aid, 0, Wid, bias, scale, Cfp16, Cid, Cext,
               M, Nc, K, blockIdx.y * 128, blockIdx.x * 128);
}

// fused Q-GEMM (z=0) + SR-conv GEMM (z=1, patch view)
__global__ void __launch_bounds__(256) hgemm_qsr(const float* bsr)
{
    extern __shared__ char smem_raw[];
    if (blockIdx.z == 0) {
        hgemm_body(smem_raw, 1, 0, 8, nullptr, 0.125f, 1, 4, nullptr,
                   BATCH * NN, DIMC, DIMC, blockIdx.y * 128, blockIdx.x * 128);
    } else {
        if (blockIdx.y >= (BATCH * NP) / 128) return;
        hgemm_body(smem_raw, -1, 1, 6, bsr, 1.f, 0, -1, nullptr,
                   BATCH * NP, DIMC, KSR, blockIdx.y * 128, blockIdx.x * 128);
    }
}

// ---------------------------------------------------------------------------
// LayerNorm: g_Xsr (fp32) -> g_Xnh (fp16). 128 threads per row.
// ---------------------------------------------------------------------------
__global__ void __launch_bounds__(128) ln_rows(const float* __restrict__ gam,
                                               const float* __restrict__ bet)
{
    const float* p = g_Xsr + (size_t)blockIdx.x * DIMC;
    __half* o = g_Xnh + (size_t)blockIdx.x * DIMC;
    int tid = threadIdx.x;
    float4 v = *(const float4*)&p[tid * 4];
    float s  = v.x + v.y + v.z + v.w;
    float sq = v.x * v.x + v.y * v.y + v.z * v.z + v.w * v.w;
#pragma unroll
    for (int off = 16; off > 0; off >>= 1) {
        s  += __shfl_xor_sync(0xffffffffu, s,  off);
        sq += __shfl_xor_sync(0xffffffffu, sq, off);
    }
    __shared__ float ss[4], sqs[4];
    int wid = tid >> 5, lid = tid & 31;
    if (lid == 0) { ss[wid] = s; sqs[wid] = sq; }
    __syncthreads();
    s  = ss[0] + ss[1] + ss[2] + ss[3];
    sq = sqs[0] + sqs[1] + sqs[2] + sqs[3];
    float mu  = s * (1.f / DIMC);
    float var = sq * (1.f / DIMC) - mu * mu;
    float inv = rsqrtf(var + 1e-5f);
    int c = tid * 4;
    float4 gm = *(const float4*)&gam[c];
    float4 bt = *(const float4*)&bet[c];
    float r0 = (v.x - mu) * inv * gm.x + bt.x;
    float r1 = (v.y - mu) * inv * gm.y + bt.y;
    float r2 = (v.z - mu) * inv * gm.z + bt.z;
    float r3 = (v.w - mu) * inv * gm.w + bt.w;
    *(uint2*)&o[c] = make_uint2(h2pack(r0, r1), h2pack(r2, r3));
}

// ---------------------------------------------------------------------------
// Flash attention, fp16 mma, cp.async double-buffered K/V, reg-resident P.
// ---------------------------------------------------------------------------
#define AST 72
#define ATT_SMEM_BYTES ((128 * AST + 2 * 64 * AST * 2) * 2)  // 55296

__global__ void __launch_bounds__(256) attn_h()
{
    extern __shared__ __align__(16) __half smh[];
    __half* Qs = smh;
    __half* Ks = Qs + 128 * AST;
    __half* Vs = Ks + 2 * 64 * AST;

    const int tid  = threadIdx.x;
    const int wid  = tid >> 5;
    const int lane = tid & 31;
    const int g = lane >> 2, t = lane & 3;
    const int qb = blockIdx.x * 128;
    const int h  = blockIdx.y;
    const int b  = blockIdx.z;

    const __half* qbase = g_Qh + ((size_t)b * NN + qb) * DIMC + h * HD;
    const __half* kvb   = g_KVh + (size_t)b * NP * 2 * DIMC + h * HD;

#pragma unroll
    for (int j = 0; j < 4; j++) {
        int id = tid + j * 256;
        int r  = id >> 3;
        int c8 = (id & 7) * 8;
        CP_ASYNC16(smem_u32(&Qs[r * AST + c8]), qbase + (size_t)r * DIMC + c8);
    }
    CP_COMMIT();

    auto issue_kv = [&](int t0, int buf) {
#pragma unroll
        for (int j = 0; j < 2; j++) {
            int id = tid + j * 256;
            int r  = id >> 3;
            int c8 = (id & 7) * 8;
            const __half* src = kvb + (size_t)(t0 + r) * (2 * DIMC) + c8;
            CP_ASYNC16(smem_u32(&Ks[(buf * 64 + r) * AST + c8]), src);
            CP_ASYNC16(smem_u32(&Vs[(buf * 64 + r) * AST + c8]), src + DIMC);
        }
        CP_COMMIT();
    };

    issue_kv(0, 0);
    CP_WAIT(1);
    __syncthreads();

    const int wq = wid * 16;
    uint32_t qf[4][4];
#pragma unroll
    for (int ks = 0; ks < 4; ks++)
        ldmx4(qf[ks], smem_u32(&Qs[(wq + (lane & 15)) * AST
                                   + ks * 16 + ((lane >> 4) << 3)]));

    float oacc[8][4];
#pragma unroll
    for (int dt = 0; dt < 8; dt++)
#pragma unroll
        for (int c = 0; c < 4; c++) oacc[dt][c] = 0.f;
    float m0r = -1e30f, m1r = -1e30f, l0r = 0.f, l1r = 0.f;

    const int niter = NP / 64;
    for (int it = 0; it < niter; it++) {
        const int buf = it & 1;
        if (it + 1 < niter) { issue_kv((it + 1) * 64, (it + 1) & 1); CP_WAIT(1); }
        else                { CP_WAIT(0); }
        __syncthreads();

        const __half* Kb = Ks + buf * 64 * AST;
        const __half* Vb = Vs + buf * 64 * AST;

        float sacc[8][4];
#pragma unroll
        for (int nt = 0; nt < 8; nt++)
#pragma unroll
            for (int c = 0; c < 4; c++) sacc[nt][c] = 0.f;
#pragma unroll
        for (int ks = 0; ks < 4; ks++) {
            uint32_t bf[4][4];
#pragma unroll
            for (int bp = 0; bp < 4; bp++)
                ldmx4(bf[bp], smem_u32(&Kb[(16 * bp + ((lane >> 4) << 3) + (lane & 7)) * AST
                                           + ks * 16 + ((lane >> 3) & 1) * 8]));
#pragma unroll
            for (int nt = 0; nt < 8; nt++)
                mma16816(sacc[nt], qf[ks][0], qf[ks][1], qf[ks][2], qf[ks][3],
                         bf[nt >> 1][(nt & 1) * 2], bf[nt >> 1][(nt & 1) * 2 + 1]);
        }

        float mn0 = m0r, mn1 = m1r;
#pragma unroll
        for (int nt = 0; nt < 8; nt++) {
            mn0 = fmaxf(mn0, fmaxf(sacc[nt][0], sacc[nt][1]));
            mn1 = fmaxf(mn1, fmaxf(sacc[nt][2], sacc[nt][3]));
        }
        mn0 = fmaxf(mn0, __shfl_xor_sync(0xffffffffu, mn0, 1));
        mn0 = fmaxf(mn0, __shfl_xor_sync(0xffffffffu, mn0, 2));
        mn1 = fmaxf(mn1, __shfl_xor_sync(0xffffffffu, mn1, 1));
        mn1 = fmaxf(mn1, __shfl_xor_sync(0xffffffffu, mn1, 2));
        float corr0 = __expf(m0r - mn0);
        float corr1 = __expf(m1r - mn1);
        m0r = mn0; m1r = mn1;
        l0r *= corr0; l1r *= corr1;
#pragma unroll
        for (int dt = 0; dt < 8; dt++) {
            oacc[dt][0] *= corr0; oacc[dt][1] *= corr0;
            oacc[dt][2] *= corr1; oacc[dt][3] *= corr1;
        }
        float ps0 = 0.f, ps1 = 0.f;
#pragma unroll
        for (int nt = 0; nt < 8; nt++) {
            sacc[nt][0] = __expf(sacc[nt][0] - mn0);
            sacc[nt][1] = __expf(sacc[nt][1] - mn0);
            sacc[nt][2] = __expf(sacc[nt][2] - mn1);
            sacc[nt][3] = __expf(sacc[nt][3] - mn1);
            ps0 += sacc[nt][0] + sacc[nt][1];
            ps1 += sacc[nt][2] + sacc[nt][3];
        }
        l0r += ps0; l1r += ps1;

        uint32_t pk[4][4];
#pragma unroll
        for (int ks = 0; ks < 4; ks++) {
            pk[ks][0] = h2pack(sacc[2 * ks][0],     sacc[2 * ks][1]);
            pk[ks][1] = h2pack(sacc[2 * ks][2],     sacc[2 * ks][3]);
            pk[ks][2] = h2pack(sacc[2 * ks + 1][0], sacc[2 * ks + 1][1]);
            pk[ks][3] = h2pack(sacc[2 * ks + 1][2], sacc[2 * ks + 1][3]);
        }

#pragma unroll
        for (int ks = 0; ks < 4; ks++) {
            uint32_t vf[4][4];
#pragma unroll
            for (int dp = 0; dp < 4; dp++)
                ldmx4t(vf[dp], smem_u32(&Vb[(16 * ks + ((lane >> 3) & 1) * 8 + (lane & 7)) * AST
                                            + 16 * dp + ((lane >> 4) << 3)]));
#pragma unroll
            for (int dt = 0; dt < 8; dt++)
                mma16816(oacc[dt], pk[ks][0], pk[ks][1], pk[ks][2], pk[ks][3],
                         vf[dt >> 1][(dt & 1) * 2], vf[dt >> 1][(dt & 1) * 2 + 1]);
        }
        __syncthreads();
    }

    l0r += __shfl_xor_sync(0xffffffffu, l0r, 1);
    l0r += __shfl_xor_sync(0xffffffffu, l0r, 2);
    l1r += __shfl_xor_sync(0xffffffffu, l1r, 1);
    l1r += __shfl_xor_sync(0xffffffffu, l1r, 2);
    const float inv0 = 1.f / l0r;
    const float inv1 = 1.f / l1r;

    const size_t orow0 = (size_t)b * NN + qb + wq + g;
#pragma unroll
    for (int dt = 0; dt < 8; dt++) {
        const int n = h * HD + dt * 8 + 2 * t;
        *(uint32_t*)&g_Oh[orow0 * DIMC + n] =
            h2pack(oacc[dt][0] * inv0, oacc[dt][1] * inv0);
        *(uint32_t*)&g_Oh[(orow0 + 8) * DIMC + n] =
            h2pack(oacc[dt][2] * inv1, oacc[dt][3] * inv1);
    }
}

// ---------------------------------------------------------------------------
// Launch
// ---------------------------------------------------------------------------
extern "C" void kernel_launch(void* const* d_in, const int* in_sizes, int n_in,
                              void* d_out, int out_size)
{
    const float* x    = (const float*)d_in[0];
    const float* Wq   = (const float*)d_in[3];
    const float* Wkv  = (const float*)d_in[4];
    const float* Wsr  = (const float*)d_in[5];
    const float* bsr  = (const float*)d_in[6];
    const float* ln_g = (const float*)d_in[7];
    const float* ln_b = (const float*)d_in[8];
    const float* Wp   = (const float*)d_in[9];
    const float* bp   = (const float*)d_in[10];
    float* out = (float*)d_out;

    cudaFuncSetAttribute(hgemm, cudaFuncAttributeMaxDynamicSharedMemorySize, G_SMEM);
    cudaFuncSetAttribute(hgemm_qsr, cudaFuncAttributeMaxDynamicSharedMemorySize, G_SMEM);
    cudaFuncSetAttribute(attn_h, cudaFuncAttributeMaxDynamicSharedMemorySize, ATT_SMEM_BYTES);

    // 0) conversions
    {
        int nx = BATCH * NN * DIMC;
        f2h_x<<<(nx / 4 + 255) / 256, 256>>>(x, nx);
        int nw = NKV + 2 * NSQ;
        f2h_w<<<(nw / 4 + 255) / 256, 256>>>(Wkv, Wq, Wp);
        wsr_reorder<<<(DIMC * KSR + 255) / 256, 256>>>(Wsr);
    }

    // 1) fused: Q = 0.125*(x @ Wq^T) -> g_Qh  AND  Xsr = im2col(x) @ Wsr^T + bsr
    hgemm_qsr<<<dim3(DIMC / 128, BATCH * NN / 128, 2), 256, G_SMEM>>>(bsr);

    // 2) LayerNorm -> fp16
    ln_rows<<<BATCH * NP, 128>>>(ln_g, ln_b);

    // 3) KV = Xn @ Wkv^T -> fp16
    hgemm<<<dim3(2 * DIMC / 128, BATCH * NP / 128), 256, G_SMEM>>>(
        2, 7, nullptr, 1.f, 1, 3, nullptr, BATCH * NP, 2 * DIMC, DIMC);

    // 4) attention
    attn_h<<<dim3(NN / 128, NHEAD, BATCH), 256, ATT_SMEM_BYTES>>>();

    // 5) out = O @ Wp^T + bp -> fp32
    hgemm<<<dim3(DIMC / 128, BATCH * NN / 128), 256, G_SMEM>>>(
        5, 9, bp, 1.f, 0, -1, out, BATCH * NN, DIMC, DIMC);
}

// round 8
// speedup vs baseline: 1.0522x; 1.0522x over previous
#include <cuda_runtime.h>
#include <cuda_fp16.h>
#include <cstdint>

// ---------------------------------------------------------------------------
// Problem constants (B=4, H=W=64, DIM=512, 8 heads, SR=2)
// ---------------------------------------------------------------------------
#define BATCH   4
#define HH      64
#define WW      64
#define NN      (HH * WW)        // 4096
#define DIMC    512
#define NHEAD   8
#define HD      (DIMC / NHEAD)   // 64
#define SRR     2
#define HP      (HH / SRR)       // 32
#define WP      (WW / SRR)       // 32
#define NP      (HP * WP)        // 1024
#define KSR     (DIMC * SRR * SRR) // 2048

// ---------------------------------------------------------------------------
// Scratch (device globals)
// ---------------------------------------------------------------------------
__device__ __half g_xh  [(size_t)BATCH * NN * DIMC];
__device__ float  g_Xsr [(size_t)BATCH * NP * DIMC];
__device__ __half g_Xnh [(size_t)BATCH * NP * DIMC];
__device__ __half g_KVh [(size_t)BATCH * NP * 2 * DIMC];
__device__ __half g_Qh  [(size_t)BATCH * NN * DIMC];
__device__ __half g_Oh  [(size_t)BATCH * NN * DIMC];
__device__ __half g_Wsrh[(size_t)DIMC * KSR];            // (o, q*512+c)
__device__ __half g_Wkvh[(size_t)2 * DIMC * DIMC];
__device__ __half g_Wqh [(size_t)DIMC * DIMC];
__device__ __half g_Wph [(size_t)DIMC * DIMC];

__device__ __forceinline__ __half* pick_h(int id) {
    switch (id) {
        case 1: return g_xh;
        case 2: return g_Xnh;
        case 3: return g_KVh;
        case 4: return g_Qh;
        case 5: return g_Oh;
        case 6: return g_Wsrh;
        case 7: return g_Wkvh;
        case 8: return g_Wqh;
        case 9: return g_Wph;
    }
    return nullptr;
}

// ---------------------------------------------------------------------------
// PTX helpers
// ---------------------------------------------------------------------------
__device__ __forceinline__ uint32_t smem_u32(const void* p) {
    uint32_t a;
    asm("{ .reg .u64 t; cvta.to.shared.u64 t, %1; cvt.u32.u64 %0, t; }"
        : "=r"(a) : "l"(p));
    return a;
}
__device__ __forceinline__ uint32_t h2pack(float a, float b) {
    __half2 h = __floats2half2_rn(a, b);
    return *(uint32_t*)&h;
}
__device__ __forceinline__ void mma16816(float c[4],
                                         uint32_t a0, uint32_t a1,
                                         uint32_t a2, uint32_t a3,
                                         uint32_t b0, uint32_t b1) {
    asm volatile(
        "mma.sync.aligned.m16n8k16.row.col.f32.f16.f16.f32 "
        "{%0,%1,%2,%3}, {%4,%5,%6,%7}, {%8,%9}, {%0,%1,%2,%3};"
        : "+f"(c[0]), "+f"(c[1]), "+f"(c[2]), "+f"(c[3])
        : "r"(a0), "r"(a1), "r"(a2), "r"(a3), "r"(b0), "r"(b1));
}
__device__ __forceinline__ void ldmx4(uint32_t r[4], uint32_t addr) {
    asm volatile(
        "ldmatrix.sync.aligned.m8n8.x4.shared.b16 {%0,%1,%2,%3}, [%4];"
        : "=r"(r[0]), "=r"(r[1]), "=r"(r[2]), "=r"(r[3]) : "r"(addr));
}
__device__ __forceinline__ void ldmx4t(uint32_t r[4], uint32_t addr) {
    asm volatile(
        "ldmatrix.sync.aligned.m8n8.x4.trans.shared.b16 {%0,%1,%2,%3}, [%4];"
        : "=r"(r[0]), "=r"(r[1]), "=r"(r[2]), "=r"(r[3]) : "r"(addr));
}
#define CP_ASYNC16(saddr, gptr) \
    asm volatile("cp.async.cg.shared.global [%0], [%1], 16;" \
        :: "r"(saddr), "l"(gptr))
#define CP_COMMIT() asm volatile("cp.async.commit_group;" ::: "memory")
#define CP_WAIT(N)  asm volatile("cp.async.wait_group %0;" :: "n"(N) : "memory")

// ---------------------------------------------------------------------------
// converts / reorder
// ---------------------------------------------------------------------------
__global__ void __launch_bounds__(256) f2h_x(const float* __restrict__ src, int n) {
    int i = (blockIdx.x * blockDim.x + threadIdx.x) * 4;
    if (i >= n) return;
    float4 v = *(const float4*)&src[i];
    *(uint2*)&g_xh[i] = make_uint2(h2pack(v.x, v.y), h2pack(v.z, v.w));
}

#define NKV (2 * DIMC * DIMC)
#define NSQ (DIMC * DIMC)
__global__ void __launch_bounds__(256) f2h_w(const float* __restrict__ wkv,
                                             const float* __restrict__ wq,
                                             const float* __restrict__ wp) {
    int i = (blockIdx.x * blockDim.x + threadIdx.x) * 4;
    const float* src;
    __half* dst;
    if (i < NKV)                { src = wkv + i;              dst = g_Wkvh + i; }
    else if (i < NKV + NSQ)     { src = wq + (i - NKV);       dst = g_Wqh  + (i - NKV); }
    else if (i < NKV + 2 * NSQ) { src = wp + (i - NKV - NSQ); dst = g_Wph  + (i - NKV - NSQ); }
    else return;
    float4 v = *(const float4*)src;
    *(uint2*)dst = make_uint2(h2pack(v.x, v.y), h2pack(v.z, v.w));
}

__global__ void __launch_bounds__(256) wsr_reorder(const float* __restrict__ wsr) {
    int idx = blockIdx.x * blockDim.x + threadIdx.x;
    if (idx >= DIMC * KSR) return;
    int o = idx >> 11, rest = idx & 2047;
    int q = rest >> 9, c = rest & 511;
    g_Wsrh[idx] = __float2half(wsr[o * 2048 + c * 4 + q]);
}

// ---------------------------------------------------------------------------
// hgemm body: 128x128 tile, BK=32, 4-stage cp.async ring, ONE sync per chunk.
// ---------------------------------------------------------------------------
#define GST 40
#define GSTAGE (128 * GST * 2)           // bytes per operand stage (10240)
#define G_SMEM (4 * GSTAGE * 2)          // 81920

__device__ __forceinline__ void hgemm_body(
    char* smem_raw, int Aid, int patchA, int Wid,
    const float* bias, float scale,
    int Cfp16, int Cid, float* Cext,
    int M, int Nc, int K, int m0, int n0)
{
    const uint32_t As0 = smem_u32(smem_raw);
    const uint32_t Bs0 = As0 + 4 * GSTAGE;

    const __half* A = patchA ? g_xh : pick_h(Aid);
    const __half* W = pick_h(Wid);

    const int tid  = threadIdx.x;
    const int wid  = tid >> 5;
    const int lane = tid & 31;
    const int g = lane >> 2, t = lane & 3;
    const int wm = (wid & 3) * 32;
    const int wn = (wid >> 2) * 64;

    const int r0 = tid >> 2;             // 0..63
    const int c8 = (tid & 3) * 8;
    int pb[2];
    if (patchA) {
#pragma unroll
        for (int j = 0; j < 2; j++) {
            int m = m0 + r0 + j * 64;
            int b = m >> 10, np = m & 1023;
            int i = np >> 5, jj = np & 31;
            pb[j] = (b << 12) + i * 128 + jj * 2;
        }
    }

    // precomputed ldmatrix offsets (bytes, relative to stage base)
    uint32_t aoff[2][2], boff[2][4];
#pragma unroll
    for (int ks = 0; ks < 2; ks++) {
        const int kcol = ks * 16 + ((lane >> 4) << 3);
#pragma unroll
        for (int mt = 0; mt < 2; mt++)
            aoff[ks][mt] = ((wm + 16 * mt + (lane & 15)) * GST + kcol) * 2;
        const int bkcol = ks * 16 + ((lane >> 3) & 1) * 8;
#pragma unroll
        for (int bp = 0; bp < 4; bp++)
            boff[ks][bp] = ((wn + 16 * bp + ((lane >> 4) << 3) + (lane & 7)) * GST + bkcol) * 2;
    }
    const uint32_t fillAoff = (r0 * GST + c8) * 2;

    float acc[2][8][4];
#pragma unroll
    for (int mt = 0; mt < 2; mt++)
#pragma unroll
        for (int nt = 0; nt < 8; nt++)
#pragma unroll
            for (int c = 0; c < 4; c++) acc[mt][nt][c] = 0.f;

    const int nch = K >> 5;

    auto issue = [&](int kc, int buf) {
        const int k0 = kc << 5;
        const uint32_t aBase = As0 + buf * GSTAGE + fillAoff;
        const uint32_t bBase = Bs0 + buf * GSTAGE + fillAoff;
        if (patchA) {
            const int q = k0 >> 9;
            const int offq = ((q >> 1) << 6) + (q & 1);
            const int cc = (k0 & 511) + c8;
#pragma unroll
            for (int j = 0; j < 2; j++) {
                CP_ASYNC16(aBase + j * 64 * GST * 2,
                           A + (size_t)(pb[j] + offq) * DIMC + cc);
                CP_ASYNC16(bBase + j * 64 * GST * 2,
                           W + (size_t)(n0 + r0 + j * 64) * K + k0 + c8);
            }
        } else {
#pragma unroll
            for (int j = 0; j < 2; j++) {
                CP_ASYNC16(aBase + j * 64 * GST * 2,
                           A + (size_t)(m0 + r0 + j * 64) * K + k0 + c8);
                CP_ASYNC16(bBase + j * 64 * GST * 2,
                           W + (size_t)(n0 + r0 + j * 64) * K + k0 + c8);
            }
        }
        CP_COMMIT();
    };

    issue(0, 0);
    issue(1, 1);
    issue(2, 2);

    for (int kc = 0; kc < nch; kc++) {
        const int rem = nch - 1 - kc;
        if (rem >= 2)      CP_WAIT(2);
        else if (rem == 1) CP_WAIT(1);
        else               CP_WAIT(0);
        __syncthreads();
        if (kc + 3 < nch) issue(kc + 3, (kc + 3) & 3);

        const uint32_t aSt = As0 + (kc & 3) * GSTAGE;
        const uint32_t bSt = Bs0 + (kc & 3) * GSTAGE;
#pragma unroll
        for (int ks = 0; ks < 2; ks++) {
            uint32_t af[2][4];
            ldmx4(af[0], aSt + aoff[ks][0]);
            ldmx4(af[1], aSt + aoff[ks][1]);
            uint32_t bf[4][4];
#pragma unroll
            for (int bp = 0; bp < 4; bp++)
                ldmx4(bf[bp], bSt + boff[ks][bp]);
#pragma unroll
            for (int nt = 0; nt < 8; nt++) {
                uint32_t b0 = bf[nt >> 1][(nt & 1) * 2];
                uint32_t b1 = bf[nt >> 1][(nt & 1) * 2 + 1];
                mma16816(acc[0][nt], af[0][0], af[0][1], af[0][2], af[0][3], b0, b1);
                mma16816(acc[1][nt], af[1][0], af[1][1], af[1][2], af[1][3], b0, b1);
            }
        }
    }

    // epilogue
    __half* Ch = Cfp16 ? pick_h(Cid) : nullptr;
    float*  Cf = Cfp16 ? nullptr : (Cext ? Cext : g_Xsr);
#pragma unroll
    for (int mt = 0; mt < 2; mt++) {
        const int mr = m0 + wm + mt * 16 + g;
#pragma unroll
        for (int nt = 0; nt < 8; nt++) {
            const int n = n0 + wn + nt * 8 + 2 * t;
            float bx = 0.f, by = 0.f;
            if (bias) { bx = bias[n]; by = bias[n + 1]; }
            float v00 = acc[mt][nt][0] * scale + bx;
            float v01 = acc[mt][nt][1] * scale + by;
            float v10 = acc[mt][nt][2] * scale + bx;
            float v11 = acc[mt][nt][3] * scale + by;
            if (Cfp16) {
                *(uint32_t*)&Ch[(size_t)mr * Nc + n]       = h2pack(v00, v01);
                *(uint32_t*)&Ch[(size_t)(mr + 8) * Nc + n] = h2pack(v10, v11);
            } else {
                *(float2*)&Cf[(size_t)mr * Nc + n]       = make_float2(v00, v01);
                *(float2*)&Cf[(size_t)(mr + 8) * Nc + n] = make_float2(v10, v11);
            }
        }
    }
}

__global__ void __launch_bounds__(256) hgemm(
    int Aid, int Wid, const float* bias, float scale,
    int Cfp16, int Cid, float* Cext, int M, int Nc, int K)
{
    extern __shared__ char smem_raw[];
    hgemm_body(smem_raw, Aid, 0, Wid, bias, scale, Cfp16, Cid, Cext,
               M, Nc, K, blockIdx.y * 128, blockIdx.x * 128);
}

__global__ void __launch_bounds__(256) hgemm_qsr(const float* bsr)
{
    extern __shared__ char smem_raw[];
    if (blockIdx.z == 0) {
        hgemm_body(smem_raw, 1, 0, 8, nullptr, 0.125f, 1, 4, nullptr,
                   BATCH * NN, DIMC, DIMC, blockIdx.y * 128, blockIdx.x * 128);
    } else {
        if (blockIdx.y >= (BATCH * NP) / 128) return;
        hgemm_body(smem_raw, -1, 1, 6, bsr, 1.f, 0, -1, nullptr,
                   BATCH * NP, DIMC, KSR, blockIdx.y * 128, blockIdx.x * 128);
    }
}

// ---------------------------------------------------------------------------
// LayerNorm: fp32 -> fp16
// ---------------------------------------------------------------------------
__global__ void __launch_bounds__(128) ln_rows(const float* __restrict__ gam,
                                               const float* __restrict__ bet)
{
    const float* p = g_Xsr + (size_t)blockIdx.x * DIMC;
    __half* o = g_Xnh + (size_t)blockIdx.x * DIMC;
    int tid = threadIdx.x;
    float4 v = *(const float4*)&p[tid * 4];
    float s  = v.x + v.y + v.z + v.w;
    float sq = v.x * v.x + v.y * v.y + v.z * v.z + v.w * v.w;
#pragma unroll
    for (int off = 16; off > 0; off >>= 1) {
        s  += __shfl_xor_sync(0xffffffffu, s,  off);
        sq += __shfl_xor_sync(0xffffffffu, sq, off);
    }
    __shared__ float ss[4], sqs[4];
    int wid = tid >> 5, lid = tid & 31;
    if (lid == 0) { ss[wid] = s; sqs[wid] = sq; }
    __syncthreads();
    s  = ss[0] + ss[1] + ss[2] + ss[3];
    sq = sqs[0] + sqs[1] + sqs[2] + sqs[3];
    float mu  = s * (1.f / DIMC);
    float var = sq * (1.f / DIMC) - mu * mu;
    float inv = rsqrtf(var + 1e-5f);
    int c = tid * 4;
    float4 gm = *(const float4*)&gam[c];
    float4 bt = *(const float4*)&bet[c];
    float r0 = (v.x - mu) * inv * gm.x + bt.x;
    float r1 = (v.y - mu) * inv * gm.y + bt.y;
    float r2 = (v.z - mu) * inv * gm.z + bt.z;
    float r3 = (v.w - mu) * inv * gm.w + bt.w;
    *(uint2*)&o[c] = make_uint2(h2pack(r0, r1), h2pack(r2, r3));
}

// ---------------------------------------------------------------------------
// Flash attention: fp16 mma, 4-stage K/V cp.async ring, ONE sync per tile.
// ---------------------------------------------------------------------------
#define AST 72
#define KVSTAGE (64 * AST * 2)           // 9216 bytes per K (or V) stage
#define ATT_SMEM_BYTES (128 * AST * 2 + 4 * KVSTAGE * 2)  // 18432 + 73728 = 92160

__global__ void __launch_bounds__(256) attn_h()
{
    extern __shared__ __align__(16) __half smh[];
    __half* Qs = smh;                          // [128][AST]
    const uint32_t Ks0 = smem_u32(smh + 128 * AST);
    const uint32_t Vs0 = Ks0 + 4 * KVSTAGE;

    const int tid  = threadIdx.x;
    const int wid  = tid >> 5;
    const int lane = tid & 31;
    const int g = lane >> 2, t = lane & 3;
    const int qb = blockIdx.x * 128;
    const int h  = blockIdx.y;
    const int b  = blockIdx.z;

    const __half* qbase = g_Qh + ((size_t)b * NN + qb) * DIMC + h * HD;
    const __half* kvb   = g_KVh + (size_t)b * NP * 2 * DIMC + h * HD;

    // Q tile (group 0)
#pragma unroll
    for (int j = 0; j < 4; j++) {
        int id = tid + j * 256;
        int r  = id >> 3;
        int c8 = (id & 7) * 8;
        CP_ASYNC16(smem_u32(&Qs[r * AST + c8]), qbase + (size_t)r * DIMC + c8);
    }
    CP_COMMIT();

    const int kr = tid >> 3;             // 0..31
    const int kc8 = (tid & 7) * 8;
    auto issue_kv = [&](int t0, int buf) {
        const uint32_t kBase = Ks0 + buf * KVSTAGE + (kr * AST + kc8) * 2;
        const uint32_t vBase = Vs0 + buf * KVSTAGE + (kr * AST + kc8) * 2;
#pragma unroll
        for (int j = 0; j < 2; j++) {
            const __half* src = kvb + (size_t)(t0 + kr + j * 32) * (2 * DIMC) + kc8;
            CP_ASYNC16(kBase + j * 32 * AST * 2, src);
            CP_ASYNC16(vBase + j * 32 * AST * 2, src + DIMC);
        }
        CP_COMMIT();
    };

    issue_kv(0, 0);
    issue_kv(64, 1);
    issue_kv(128, 2);
    CP_WAIT(3);           // Q complete
    __syncthreads();

    const int wq = wid * 16;
    uint32_t qf[4][4];
#pragma unroll
    for (int ks = 0; ks < 4; ks++)
        ldmx4(qf[ks], smem_u32(&Qs[(wq + (lane & 15)) * AST
                                   + ks * 16 + ((lane >> 4) << 3)]));

    // precomputed K/V ldmatrix offsets (relative to stage base)
    uint32_t koff[4][4], voff[4][4];
#pragma unroll
    for (int ks = 0; ks < 4; ks++) {
#pragma unroll
        for (int bp = 0; bp < 4; bp++)
            koff[ks][bp] = ((16 * bp + ((lane >> 4) << 3) + (lane & 7)) * AST
                            + ks * 16 + ((lane >> 3) & 1) * 8) * 2;
#pragma unroll
        for (int dp = 0; dp < 4; dp++)
            voff[ks][dp] = ((16 * ks + ((lane >> 3) & 1) * 8 + (lane & 7)) * AST
                            + 16 * dp + ((lane >> 4) << 3)) * 2;
    }

    float oacc[8][4];
#pragma unroll
    for (int dt = 0; dt < 8; dt++)
#pragma unroll
        for (int c = 0; c < 4; c++) oacc[dt][c] = 0.f;
    float m0r = -1e30f, m1r = -1e30f, l0r = 0.f, l1r = 0.f;

    const int niter = NP / 64;
    for (int it = 0; it < niter; it++) {
        const int rem = niter - 1 - it;
        if (rem >= 2)      CP_WAIT(2);
        else if (rem == 1) CP_WAIT(1);
        else               CP_WAIT(0);
        __syncthreads();
        if (it + 3 < niter) issue_kv((it + 3) * 64, (it + 3) & 3);

        const uint32_t Kb = Ks0 + (it & 3) * KVSTAGE;
        const uint32_t Vb = Vs0 + (it & 3) * KVSTAGE;

        float sacc[8][4];
#pragma unroll
        for (int nt = 0; nt < 8; nt++)
#pragma unroll
            for (int c = 0; c < 4; c++) sacc[nt][c] = 0.f;
#pragma unroll
        for (int ks = 0; ks < 4; ks++) {
            uint32_t bf[4][4];
#pragma unroll
            for (int bp = 0; bp < 4; bp++)
                ldmx4(bf[bp], Kb + koff[ks][bp]);
#pragma unroll
            for (int nt = 0; nt < 8; nt++)
                mma16816(sacc[nt], qf[ks][0], qf[ks][1], qf[ks][2], qf[ks][3],
                         bf[nt >> 1][(nt & 1) * 2], bf[nt >> 1][(nt & 1) * 2 + 1]);
        }

        float mn0 = m0r, mn1 = m1r;
#pragma unroll
        for (int nt = 0; nt < 8; nt++) {
            mn0 = fmaxf(mn0, fmaxf(sacc[nt][0], sacc[nt][1]));
            mn1 = fmaxf(mn1, fmaxf(sacc[nt][2], sacc[nt][3]));
        }
        mn0 = fmaxf(mn0, __shfl_xor_sync(0xffffffffu, mn0, 1));
        mn0 = fmaxf(mn0, __shfl_xor_sync(0xffffffffu, mn0, 2));
        mn1 = fmaxf(mn1, __shfl_xor_sync(0xffffffffu, mn1, 1));
        mn1 = fmaxf(mn1, __shfl_xor_sync(0xffffffffu, mn1, 2));
        float corr0 = __expf(m0r - mn0);
        float corr1 = __expf(m1r - mn1);
        m0r = mn0; m1r = mn1;
        l0r *= corr0; l1r *= corr1;
#pragma unroll
        for (int dt = 0; dt < 8; dt++) {
            oacc[dt][0] *= corr0; oacc[dt][1] *= corr0;
            oacc[dt][2] *= corr1; oacc[dt][3] *= corr1;
        }
        float ps0 = 0.f, ps1 = 0.f;
#pragma unroll
        for (int nt = 0; nt < 8; nt++) {
            sacc[nt][0] = __expf(sacc[nt][0] - mn0);
            sacc[nt][1] = __expf(sacc[nt][1] - mn0);
            sacc[nt][2] = __expf(sacc[nt][2] - mn1);
            sacc[nt][3] = __expf(sacc[nt][3] - mn1);
            ps0 += sacc[nt][0] + sacc[nt][1];
            ps1 += sacc[nt][2] + sacc[nt][3];
        }
        l0r += ps0; l1r += ps1;

        uint32_t pk[4][4];
#pragma unroll
        for (int ks = 0; ks < 4; ks++) {
            pk[ks][0] = h2pack(sacc[2 * ks][0],     sacc[2 * ks][1]);
            pk[ks][1] = h2pack(sacc[2 * ks][2],     sacc[2 * ks][3]);
            pk[ks][2] = h2pack(sacc[2 * ks + 1][0], sacc[2 * ks + 1][1]);
            pk[ks][3] = h2pack(sacc[2 * ks + 1][2], sacc[2 * ks + 1][3]);
        }

#pragma unroll
        for (int ks = 0; ks < 4; ks++) {
            uint32_t vf[4][4];
#pragma unroll
            for (int dp = 0; dp < 4; dp++)
                ldmx4t(vf[dp], Vb + voff[ks][dp]);
#pragma unroll
            for (int dt = 0; dt < 8; dt++)
                mma16816(oacc[dt], pk[ks][0], pk[ks][1], pk[ks][2], pk[ks][3],
                         vf[dt >> 1][(dt & 1) * 2], vf[dt >> 1][(dt & 1) * 2 + 1]);
        }
    }

    l0r += __shfl_xor_sync(0xffffffffu, l0r, 1);
    l0r += __shfl_xor_sync(0xffffffffu, l0r, 2);
    l1r += __shfl_xor_sync(0xffffffffu, l1r, 1);
    l1r += __shfl_xor_sync(0xffffffffu, l1r, 2);
    const float inv0 = 1.f / l0r;
    const float inv1 = 1.f / l1r;

    const size_t orow0 = (size_t)b * NN + qb + wq + g;
#pragma unroll
    for (int dt = 0; dt < 8; dt++) {
        const int n = h * HD + dt * 8 + 2 * t;
        *(uint32_t*)&g_Oh[orow0 * DIMC + n] =
            h2pack(oacc[dt][0] * inv0, oacc[dt][1] * inv0);
        *(uint32_t*)&g_Oh[(orow0 + 8) * DIMC + n] =
            h2pack(oacc[dt][2] * inv1, oacc[dt][3] * inv1);
    }
}

// ---------------------------------------------------------------------------
// Launch
// ---------------------------------------------------------------------------
extern "C" void kernel_launch(void* const* d_in, const int* in_sizes, int n_in,
                              void* d_out, int out_size)
{
    const float* x    = (const float*)d_in[0];
    const float* Wq   = (const float*)d_in[3];
    const float* Wkv  = (const float*)d_in[4];
    const float* Wsr  = (const float*)d_in[5];
    const float* bsr  = (const float*)d_in[6];
    const float* ln_g = (const float*)d_in[7];
    const float* ln_b = (const float*)d_in[8];
    const float* Wp   = (const float*)d_in[9];
    const float* bp   = (const float*)d_in[10];
    float* out = (float*)d_out;

    cudaFuncSetAttribute(hgemm, cudaFuncAttributeMaxDynamicSharedMemorySize, G_SMEM);
    cudaFuncSetAttribute(hgemm_qsr, cudaFuncAttributeMaxDynamicSharedMemorySize, G_SMEM);
    cudaFuncSetAttribute(attn_h, cudaFuncAttributeMaxDynamicSharedMemorySize, ATT_SMEM_BYTES);

    {
        int nx = BATCH * NN * DIMC;
        f2h_x<<<(nx / 4 + 255) / 256, 256>>>(x, nx);
        int nw = NKV + 2 * NSQ;
        f2h_w<<<(nw / 4 + 255) / 256, 256>>>(Wkv, Wq, Wp);
        wsr_reorder<<<(DIMC * KSR + 255) / 256, 256>>>(Wsr);
    }

    // fused: Q = 0.125*(x @ Wq^T)  AND  Xsr = im2col(x) @ Wsr^T + bsr
    hgemm_qsr<<<dim3(DIMC / 128, BATCH * NN / 128, 2), 256, G_SMEM>>>(bsr);

    ln_rows<<<BATCH * NP, 128>>>(ln_g, ln_b);

    hgemm<<<dim3(2 * DIMC / 128, BATCH * NP / 128), 256, G_SMEM>>>(
        2, 7, nullptr, 1.f, 1, 3, nullptr, BATCH * NP, 2 * DIMC, DIMC);

    attn_h<<<dim3(NN / 128, NHEAD, BATCH), 256, ATT_SMEM_BYTES>>>();

    hgemm<<<dim3(DIMC / 128, BATCH * NN / 128), 256, G_SMEM>>>(
        5, 9, bp, 1.f, 0, -1, out, BATCH * NN, DIMC, DIMC);
}

// round 10
// speedup vs baseline: 1.1667x; 1.1088x over previous
#include <cuda_runtime.h>
#include <cuda_fp16.h>
#include <cstdint>

// ---------------------------------------------------------------------------
// Problem constants (B=4, H=W=64, DIM=512, 8 heads, SR=2)
// ---------------------------------------------------------------------------
#define BATCH   4
#define HH      64
#define WW      64
#define NN      (HH * WW)        // 4096
#define DIMC    512
#define NHEAD   8
#define HD      (DIMC / NHEAD)   // 64
#define SRR     2
#define HP      (HH / SRR)       // 32
#define WP      (WW / SRR)       // 32
#define NP      (HP * WP)        // 1024
#define KSR     (DIMC * SRR * SRR) // 2048

// ---------------------------------------------------------------------------
// Scratch (device globals)
// ---------------------------------------------------------------------------
__device__ __half g_xh  [(size_t)BATCH * NN * DIMC];
__device__ float  g_Xsr [(size_t)BATCH * NP * DIMC];
__device__ __half g_Xnh [(size_t)BATCH * NP * DIMC];
__device__ __half g_KVh [(size_t)BATCH * NP * 2 * DIMC];
__device__ __half g_Qh  [(size_t)BATCH * NN * DIMC];
__device__ __half g_Oh  [(size_t)BATCH * NN * DIMC];
__device__ __half g_Wsrh[(size_t)DIMC * KSR];            // (o, q*512+c)
__device__ __half g_Wkvh[(size_t)2 * DIMC * DIMC];
__device__ __half g_Wqh [(size_t)DIMC * DIMC];
__device__ __half g_Wph [(size_t)DIMC * DIMC];

__device__ __forceinline__ __half* pick_h(int id) {
    switch (id) {
        case 1: return g_xh;
        case 2: return g_Xnh;
        case 3: return g_KVh;
        case 4: return g_Qh;
        case 5: return g_Oh;
        case 6: return g_Wsrh;
        case 7: return g_Wkvh;
        case 8: return g_Wqh;
        case 9: return g_Wph;
    }
    return nullptr;
}

// ---------------------------------------------------------------------------
// PTX helpers
// ---------------------------------------------------------------------------
__device__ __forceinline__ uint32_t smem_u32(const void* p) {
    uint32_t a;
    asm("{ .reg .u64 t; cvta.to.shared.u64 t, %1; cvt.u32.u64 %0, t; }"
        : "=r"(a) : "l"(p));
    return a;
}
__device__ __forceinline__ uint32_t h2pack(float a, float b) {
    __half2 h = __floats2half2_rn(a, b);
    return *(uint32_t*)&h;
}
__device__ __forceinline__ void mma16816(float c[4],
                                         uint32_t a0, uint32_t a1,
                                         uint32_t a2, uint32_t a3,
                                         uint32_t b0, uint32_t b1) {
    asm volatile(
        "mma.sync.aligned.m16n8k16.row.col.f32.f16.f16.f32 "
        "{%0,%1,%2,%3}, {%4,%5,%6,%7}, {%8,%9}, {%0,%1,%2,%3};"
        : "+f"(c[0]), "+f"(c[1]), "+f"(c[2]), "+f"(c[3])
        : "r"(a0), "r"(a1), "r"(a2), "r"(a3), "r"(b0), "r"(b1));
}
__device__ __forceinline__ void ldmx4(uint32_t r[4], uint32_t addr) {
    asm volatile(
        "ldmatrix.sync.aligned.m8n8.x4.shared.b16 {%0,%1,%2,%3}, [%4];"
        : "=r"(r[0]), "=r"(r[1]), "=r"(r[2]), "=r"(r[3]) : "r"(addr));
}
__device__ __forceinline__ void ldmx4t(uint32_t r[4], uint32_t addr) {
    asm volatile(
        "ldmatrix.sync.aligned.m8n8.x4.trans.shared.b16 {%0,%1,%2,%3}, [%4];"
        : "=r"(r[0]), "=r"(r[1]), "=r"(r[2]), "=r"(r[3]) : "r"(addr));
}
#define CP_ASYNC16(saddr, gptr) \
    asm volatile("cp.async.cg.shared.global [%0], [%1], 16;" \
        :: "r"(saddr), "l"(gptr))
#define CP_COMMIT() asm volatile("cp.async.commit_group;" ::: "memory")
#define CP_WAIT(N)  asm volatile("cp.async.wait_group %0;" :: "n"(N) : "memory")

// ---------------------------------------------------------------------------
// converts / reorder
// ---------------------------------------------------------------------------
__global__ void __launch_bounds__(256) f2h_x(const float* __restrict__ src, int n) {
    int i = (blockIdx.x * blockDim.x + threadIdx.x) * 4;
    if (i >= n) return;
    float4 v = *(const float4*)&src[i];
    *(uint2*)&g_xh[i] = make_uint2(h2pack(v.x, v.y), h2pack(v.z, v.w));
}

#define NKV (2 * DIMC * DIMC)
#define NSQ (DIMC * DIMC)
__global__ void __launch_bounds__(256) f2h_w(const float* __restrict__ wkv,
                                             const float* __restrict__ wq,
                                             const float* __restrict__ wp) {
    int i = (blockIdx.x * blockDim.x + threadIdx.x) * 4;
    const float* src;
    __half* dst;
    if (i < NKV)                { src = wkv + i;              dst = g_Wkvh + i; }
    else if (i < NKV + NSQ)     { src = wq + (i - NKV);       dst = g_Wqh  + (i - NKV); }
    else if (i < NKV + 2 * NSQ) { src = wp + (i - NKV - NSQ); dst = g_Wph  + (i - NKV - NSQ); }
    else return;
    float4 v = *(const float4*)src;
    *(uint2*)dst = make_uint2(h2pack(v.x, v.y), h2pack(v.z, v.w));
}

__global__ void __launch_bounds__(256) wsr_reorder(const float* __restrict__ wsr) {
    int idx = blockIdx.x * blockDim.x + threadIdx.x;
    if (idx >= DIMC * KSR) return;
    int o = idx >> 11, rest = idx & 2047;
    int q = rest >> 9, c = rest & 511;
    g_Wsrh[idx] = __float2half(wsr[o * 2048 + c * 4 + q]);
}

// ---------------------------------------------------------------------------
// hgemm body: 128x128 tile, BK=64, 3-stage cp.async ring, ONE sync per chunk.
// ---------------------------------------------------------------------------
#define GST 72
#define GSTAGE (128 * GST * 2)           // 18432 bytes per operand stage
#define G_SMEM (3 * GSTAGE * 2)          // 110592

__device__ __forceinline__ void hgemm_body(
    char* smem_raw, int Aid, int patchA, int Wid,
    const float* bias, float scale,
    int Cfp16, int Cid, float* Cext,
    int M, int Nc, int K, int m0, int n0)
{
    const uint32_t As0 = smem_u32(smem_raw);
    const uint32_t Bs0 = As0 + 3 * GSTAGE;

    const __half* A = patchA ? g_xh : pick_h(Aid);
    const __half* W = pick_h(Wid);

    const int tid  = threadIdx.x;
    const int wid  = tid >> 5;
    const int lane = tid & 31;
    const int g = lane >> 2, t = lane & 3;
    const int wm = (wid & 3) * 32;
    const int wn = (wid >> 2) * 64;

    const int r0 = tid >> 2;             // 0..63
    const int cb = (tid & 3) * 16;       // 0,16,32,48 (halfs)
    int pb[2];
    if (patchA) {
#pragma unroll
        for (int j = 0; j < 2; j++) {
            int m = m0 + r0 + j * 64;
            int b = m >> 10, np = m & 1023;
            int i = np >> 5, jj = np & 31;
            pb[j] = (b << 12) + i * 128 + jj * 2;
        }
    }

    // ldmatrix offsets (bytes, relative to stage base), 4 ksteps
    uint32_t aoff[4][2], boff[4][4];
#pragma unroll
    for (int ks = 0; ks < 4; ks++) {
        const int kcol = ks * 16 + ((lane >> 4) << 3);
#pragma unroll
        for (int mt = 0; mt < 2; mt++)
            aoff[ks][mt] = ((wm + 16 * mt + (lane & 15)) * GST + kcol) * 2;
        const int bkcol = ks * 16 + ((lane >> 3) & 1) * 8;
#pragma unroll
        for (int bp = 0; bp < 4; bp++)
            boff[ks][bp] = ((wn + 16 * bp + ((lane >> 4) << 3) + (lane & 7)) * GST + bkcol) * 2;
    }
    const uint32_t fillOff = (r0 * GST + cb) * 2;

    float acc[2][8][4];
#pragma unroll
    for (int mt = 0; mt < 2; mt++)
#pragma unroll
        for (int nt = 0; nt < 8; nt++)
#pragma unroll
            for (int c = 0; c < 4; c++) acc[mt][nt][c] = 0.f;

    const int nch = K >> 6;

    auto issue = [&](int kc, int buf) {
        const int k0 = kc << 6;
        const uint32_t aBase = As0 + buf * GSTAGE + fillOff;
        const uint32_t bBase = Bs0 + buf * GSTAGE + fillOff;
        if (patchA) {
            const int q = k0 >> 9;
            const int offq = ((q >> 1) << 6) + (q & 1);
            const int cc = (k0 & 511) + cb;
#pragma unroll
            for (int j = 0; j < 2; j++) {
                const __half* ap = A + (size_t)(pb[j] + offq) * DIMC + cc;
                const __half* wp = W + (size_t)(n0 + r0 + j * 64) * K + k0 + cb;
                CP_ASYNC16(aBase + j * 64 * GST * 2,      ap);
                CP_ASYNC16(aBase + j * 64 * GST * 2 + 16, ap + 8);
                CP_ASYNC16(bBase + j * 64 * GST * 2,      wp);
                CP_ASYNC16(bBase + j * 64 * GST * 2 + 16, wp + 8);
            }
        } else {
#pragma unroll
            for (int j = 0; j < 2; j++) {
                const __half* ap = A + (size_t)(m0 + r0 + j * 64) * K + k0 + cb;
                const __half* wp = W + (size_t)(n0 + r0 + j * 64) * K + k0 + cb;
                CP_ASYNC16(aBase + j * 64 * GST * 2,      ap);
                CP_ASYNC16(aBase + j * 64 * GST * 2 + 16, ap + 8);
                CP_ASYNC16(bBase + j * 64 * GST * 2,      wp);
                CP_ASYNC16(bBase + j * 64 * GST * 2 + 16, wp + 8);
            }
        }
        CP_COMMIT();
    };

    issue(0, 0);
    if (nch > 1) issue(1, 1);

    int buf = 0;
    for (int kc = 0; kc < nch; kc++) {
        const int rem = nch - 1 - kc;
        if (rem >= 1) CP_WAIT(1);
        else          CP_WAIT(0);
        __syncthreads();
        if (kc + 2 < nch) issue(kc + 2, (kc + 2) % 3);

        const uint32_t aSt = As0 + buf * GSTAGE;
        const uint32_t bSt = Bs0 + buf * GSTAGE;
#pragma unroll
        for (int ks = 0; ks < 4; ks++) {
            uint32_t af[2][4];
            ldmx4(af[0], aSt + aoff[ks][0]);
            ldmx4(af[1], aSt + aoff[ks][1]);
            uint32_t bf[4][4];
#pragma unroll
            for (int bp = 0; bp < 4; bp++)
                ldmx4(bf[bp], bSt + boff[ks][bp]);
#pragma unroll
            for (int nt = 0; nt < 8; nt++) {
                uint32_t b0 = bf[nt >> 1][(nt & 1) * 2];
                uint32_t b1 = bf[nt >> 1][(nt & 1) * 2 + 1];
                mma16816(acc[0][nt], af[0][0], af[0][1], af[0][2], af[0][3], b0, b1);
                mma16816(acc[1][nt], af[1][0], af[1][1], af[1][2], af[1][3], b0, b1);
            }
        }
        buf = buf == 2 ? 0 : buf + 1;
    }

    // epilogue
    __half* Ch = Cfp16 ? pick_h(Cid) : nullptr;
    float*  Cf = Cfp16 ? nullptr : (Cext ? Cext : g_Xsr);
#pragma unroll
    for (int mt = 0; mt < 2; mt++) {
        const int mr = m0 + wm + mt * 16 + g;
#pragma unroll
        for (int nt = 0; nt < 8; nt++) {
            const int n = n0 + wn + nt * 8 + 2 * t;
            float bx = 0.f, by = 0.f;
            if (bias) { bx = bias[n]; by = bias[n + 1]; }
            float v00 = acc[mt][nt][0] * scale + bx;
            float v01 = acc[mt][nt][1] * scale + by;
            float v10 = acc[mt][nt][2] * scale + bx;
            float v11 = acc[mt][nt][3] * scale + by;
            if (Cfp16) {
                *(uint32_t*)&Ch[(size_t)mr * Nc + n]       = h2pack(v00, v01);
                *(uint32_t*)&Ch[(size_t)(mr + 8) * Nc + n] = h2pack(v10, v11);
            } else {
                *(float2*)&Cf[(size_t)mr * Nc + n]       = make_float2(v00, v01);
                *(float2*)&Cf[(size_t)(mr + 8) * Nc + n] = make_float2(v10, v11);
            }
        }
    }
}

__global__ void __launch_bounds__(256) hgemm(
    int Aid, int Wid, const float* bias, float scale,
    int Cfp16, int Cid, float* Cext, int M, int Nc, int K)
{
    extern __shared__ char smem_raw[];
    hgemm_body(smem_raw, Aid, 0, Wid, bias, scale, Cfp16, Cid, Cext,
               M, Nc, K, blockIdx.y * 128, blockIdx.x * 128);
}

// fused: y<32 -> SR-conv (long jobs, scheduled FIRST), y>=32 -> Q-GEMM
__global__ void __launch_bounds__(256) hgemm_qsr(const float* bsr)
{
    extern __shared__ char smem_raw[];
    if (blockIdx.y < 32) {
        hgemm_body(smem_raw, -1, 1, 6, bsr, 1.f, 0, -1, nullptr,
                   BATCH * NP, DIMC, KSR, blockIdx.y * 128, blockIdx.x * 128);
    } else {
        hgemm_body(smem_raw, 1, 0, 8, nullptr, 0.125f, 1, 4, nullptr,
                   BATCH * NN, DIMC, DIMC, (blockIdx.y - 32) * 128, blockIdx.x * 128);
    }
}

// ---------------------------------------------------------------------------
// LayerNorm: fp32 -> fp16
// ---------------------------------------------------------------------------
__global__ void __launch_bounds__(128) ln_rows(const float* __restrict__ gam,
                                               const float* __restrict__ bet)
{
    const float* p = g_Xsr + (size_t)blockIdx.x * DIMC;
    __half* o = g_Xnh + (size_t)blockIdx.x * DIMC;
    int tid = threadIdx.x;
    float4 v = *(const float4*)&p[tid * 4];
    float s  = v.x + v.y + v.z + v.w;
    float sq = v.x * v.x + v.y * v.y + v.z * v.z + v.w * v.w;
#pragma unroll
    for (int off = 16; off > 0; off >>= 1) {
        s  += __shfl_xor_sync(0xffffffffu, s,  off);
        sq += __shfl_xor_sync(0xffffffffu, sq, off);
    }
    __shared__ float ss[4], sqs[4];
    int wid = tid >> 5, lid = tid & 31;
    if (lid == 0) { ss[wid] = s; sqs[wid] = sq; }
    __syncthreads();
    s  = ss[0] + ss[1] + ss[2] + ss[3];
    sq = sqs[0] + sqs[1] + sqs[2] + sqs[3];
    float mu  = s * (1.f / DIMC);
    float var = sq * (1.f / DIMC) - mu * mu;
    float inv = rsqrtf(var + 1e-5f);
    int c = tid * 4;
    float4 gm = *(const float4*)&gam[c];
    float4 bt = *(const float4*)&bet[c];
    float r0 = (v.x - mu) * inv * gm.x + bt.x;
    float r1 = (v.y - mu) * inv * gm.y + bt.y;
    float r2 = (v.z - mu) * inv * gm.z + bt.z;
    float r3 = (v.w - mu) * inv * gm.w + bt.w;
    *(uint2*)&o[c] = make_uint2(h2pack(r0, r1), h2pack(r2, r3));
}

// ---------------------------------------------------------------------------
// Flash attention: fp16 mma, 4-stage K/V cp.async ring, ONE sync per tile.
// ---------------------------------------------------------------------------
#define AST 72
#define KVSTAGE (64 * AST * 2)           // 9216 bytes
#define ATT_SMEM_BYTES (128 * AST * 2 + 4 * KVSTAGE * 2)  // 92160

__global__ void __launch_bounds__(256) attn_h()
{
    extern __shared__ __align__(16) __half smh[];
    __half* Qs = smh;
    const uint32_t Ks0 = smem_u32(smh + 128 * AST);
    const uint32_t Vs0 = Ks0 + 4 * KVSTAGE;

    const int tid  = threadIdx.x;
    const int wid  = tid >> 5;
    const int lane = tid & 31;
    const int g = lane >> 2, t = lane & 3;
    const int qb = blockIdx.x * 128;
    const int h  = blockIdx.y;
    const int b  = blockIdx.z;

    const __half* qbase = g_Qh + ((size_t)b * NN + qb) * DIMC + h * HD;
    const __half* kvb   = g_KVh + (size_t)b * NP * 2 * DIMC + h * HD;

#pragma unroll
    for (int j = 0; j < 4; j++) {
        int id = tid + j * 256;
        int r  = id >> 3;
        int c8 = (id & 7) * 8;
        CP_ASYNC16(smem_u32(&Qs[r * AST + c8]), qbase + (size_t)r * DIMC + c8);
    }
    CP_COMMIT();

    const int kr = tid >> 3;
    const int kc8 = (tid & 7) * 8;
    auto issue_kv = [&](int t0, int buf) {
        const uint32_t kBase = Ks0 + buf * KVSTAGE + (kr * AST + kc8) * 2;
        const uint32_t vBase = Vs0 + buf * KVSTAGE + (kr * AST + kc8) * 2;
#pragma unroll
        for (int j = 0; j < 2; j++) {
            const __half* src = kvb + (size_t)(t0 + kr + j * 32) * (2 * DIMC) + kc8;
            CP_ASYNC16(kBase + j * 32 * AST * 2, src);
            CP_ASYNC16(vBase + j * 32 * AST * 2, src + DIMC);
        }
        CP_COMMIT();
    };

    issue_kv(0, 0);
    issue_kv(64, 1);
    issue_kv(128, 2);
    CP_WAIT(3);
    __syncthreads();

    const int wq = wid * 16;
    uint32_t qf[4][4];
#pragma unroll
    for (int ks = 0; ks < 4; ks++)
        ldmx4(qf[ks], smem_u32(&Qs[(wq + (lane & 15)) * AST
                                   + ks * 16 + ((lane >> 4) << 3)]));

    uint32_t koff[4][4], voff[4][4];
#pragma unroll
    for (int ks = 0; ks < 4; ks++) {
#pragma unroll
        for (int bp = 0; bp < 4; bp++)
            koff[ks][bp] = ((16 * bp + ((lane >> 4) << 3) + (lane & 7)) * AST
                            + ks * 16 + ((lane >> 3) & 1) * 8) * 2;
#pragma unroll
        for (int dp = 0; dp < 4; dp++)
            voff[ks][dp] = ((16 * ks + ((lane >> 3) & 1) * 8 + (lane & 7)) * AST
                            + 16 * dp + ((lane >> 4) << 3)) * 2;
    }

    float oacc[8][4];
#pragma unroll
    for (int dt = 0; dt < 8; dt++)
#pragma unroll
        for (int c = 0; c < 4; c++) oacc[dt][c] = 0.f;
    float m0r = -1e30f, m1r = -1e30f, l0r = 0.f, l1r = 0.f;

    const int niter = NP / 64;
    for (int it = 0; it < niter; it++) {
        const int rem = niter - 1 - it;
        if (rem >= 2)      CP_WAIT(2);
        else if (rem == 1) CP_WAIT(1);
        else               CP_WAIT(0);
        __syncthreads();
        if (it + 3 < niter) issue_kv((it + 3) * 64, (it + 3) & 3);

        const uint32_t Kb = Ks0 + (it & 3) * KVSTAGE;
        const uint32_t Vb = Vs0 + (it & 3) * KVSTAGE;

        float sacc[8][4];
#pragma unroll
        for (int nt = 0; nt < 8; nt++)
#pragma unroll
            for (int c = 0; c < 4; c++) sacc[nt][c] = 0.f;
#pragma unroll
        for (int ks = 0; ks < 4; ks++) {
            uint32_t bf[4][4];
#pragma unroll
            for (int bp = 0; bp < 4; bp++)
                ldmx4(bf[bp], Kb + koff[ks][bp]);
#pragma unroll
            for (int nt = 0; nt < 8; nt++)
                mma16816(sacc[nt], qf[ks][0], qf[ks][1], qf[ks][2], qf[ks][3],
                         bf[nt >> 1][(nt & 1) * 2], bf[nt >> 1][(nt & 1) * 2 + 1]);
        }

        float mn0 = m0r, mn1 = m1r;
#pragma unroll
        for (int nt = 0; nt < 8; nt++) {
            mn0 = fmaxf(mn0, fmaxf(sacc[nt][0], sacc[nt][1]));
            mn1 = fmaxf(mn1, fmaxf(sacc[nt][2], sacc[nt][3]));
        }
        mn0 = fmaxf(mn0, __shfl_xor_sync(0xffffffffu, mn0, 1));
        mn0 = fmaxf(mn0, __shfl_xor_sync(0xffffffffu, mn0, 2));
        mn1 = fmaxf(mn1, __shfl_xor_sync(0xffffffffu, mn1, 1));
        mn1 = fmaxf(mn1, __shfl_xor_sync(0xffffffffu, mn1, 2));
        float corr0 = __expf(m0r - mn0);
        float corr1 = __expf(m1r - mn1);
        m0r = mn0; m1r = mn1;
        l0r *= corr0; l1r *= corr1;
#pragma unroll
        for (int dt = 0; dt < 8; dt++) {
            oacc[dt][0] *= corr0; oacc[dt][1] *= corr0;
            oacc[dt][2] *= corr1; oacc[dt][3] *= corr1;
        }
        float ps0 = 0.f, ps1 = 0.f;
#pragma unroll
        for (int nt = 0; nt < 8; nt++) {
            sacc[nt][0] = __expf(sacc[nt][0] - mn0);
            sacc[nt][1] = __expf(sacc[nt][1] - mn0);
            sacc[nt][2] = __expf(sacc[nt][2] - mn1);
            sacc[nt][3] = __expf(sacc[nt][3] - mn1);
            ps0 += sacc[nt][0] + sacc[nt][1];
            ps1 += sacc[nt][2] + sacc[nt][3];
        }
        l0r += ps0; l1r += ps1;

        uint32_t pk[4][4];
#pragma unroll
        for (int ks = 0; ks < 4; ks++) {
            pk[ks][0] = h2pack(sacc[2 * ks][0],     sacc[2 * ks][1]);
            pk[ks][1] = h2pack(sacc[2 * ks][2],     sacc[2 * ks][3]);
            pk[ks][2] = h2pack(sacc[2 * ks + 1][0], sacc[2 * ks + 1][1]);
            pk[ks][3] = h2pack(sacc[2 * ks + 1][2], sacc[2 * ks + 1][3]);
        }

#pragma unroll
        for (int ks = 0; ks < 4; ks++) {
            uint32_t vf[4][4];
#pragma unroll
            for (int dp = 0; dp < 4; dp++)
                ldmx4t(vf[dp], Vb + voff[ks][dp]);
#pragma unroll
            for (int dt = 0; dt < 8; dt++)
                mma16816(oacc[dt], pk[ks][0], pk[ks][1], pk[ks][2], pk[ks][3],
                         vf[dt >> 1][(dt & 1) * 2], vf[dt >> 1][(dt & 1) * 2 + 1]);
        }
    }

    l0r += __shfl_xor_sync(0xffffffffu, l0r, 1);
    l0r += __shfl_xor_sync(0xffffffffu, l0r, 2);
    l1r += __shfl_xor_sync(0xffffffffu, l1r, 1);
    l1r += __shfl_xor_sync(0xffffffffu, l1r, 2);
    const float inv0 = 1.f / l0r;
    const float inv1 = 1.f / l1r;

    const size_t orow0 = (size_t)b * NN + qb + wq + g;
#pragma unroll
    for (int dt = 0; dt < 8; dt++) {
        const int n = h * HD + dt * 8 + 2 * t;
        *(uint32_t*)&g_Oh[orow0 * DIMC + n] =
            h2pack(oacc[dt][0] * inv0, oacc[dt][1] * inv0);
        *(uint32_t*)&g_Oh[(orow0 + 8) * DIMC + n] =
            h2pack(oacc[dt][2] * inv1, oacc[dt][3] * inv1);
    }
}

// ---------------------------------------------------------------------------
// Launch
// ---------------------------------------------------------------------------
extern "C" void kernel_launch(void* const* d_in, const int* in_sizes, int n_in,
                              void* d_out, int out_size)
{
    const float* x    = (const float*)d_in[0];
    const float* Wq   = (const float*)d_in[3];
    const float* Wkv  = (const float*)d_in[4];
    const float* Wsr  = (const float*)d_in[5];
    const float* bsr  = (const float*)d_in[6];
    const float* ln_g = (const float*)d_in[7];
    const float* ln_b = (const float*)d_in[8];
    const float* Wp   = (const float*)d_in[9];
    const float* bp   = (const float*)d_in[10];
    float* out = (float*)d_out;

    cudaFuncSetAttribute(hgemm, cudaFuncAttributeMaxDynamicSharedMemorySize, G_SMEM);
    cudaFuncSetAttribute(hgemm_qsr, cudaFuncAttributeMaxDynamicSharedMemorySize, G_SMEM);
    cudaFuncSetAttribute(attn_h, cudaFuncAttributeMaxDynamicSharedMemorySize, ATT_SMEM_BYTES);

    {
        int nx = BATCH * NN * DIMC;
        f2h_x<<<(nx / 4 + 255) / 256, 256>>>(x, nx);
        int nw = NKV + 2 * NSQ;
        f2h_w<<<(nw / 4 + 255) / 256, 256>>>(Wkv, Wq, Wp);
        wsr_reorder<<<(DIMC * KSR + 255) / 256, 256>>>(Wsr);
    }

    // fused: SR-conv (y<32, long) + Q-GEMM (y>=32, short) — longest-first order
    hgemm_qsr<<<dim3(DIMC / 128, 160), 256, G_SMEM>>>(bsr);

    ln_rows<<<BATCH * NP, 128>>>(ln_g, ln_b);

    hgemm<<<dim3(2 * DIMC / 128, BATCH * NP / 128), 256, G_SMEM>>>(
        2, 7, nullptr, 1.f, 1, 3, nullptr, BATCH * NP, 2 * DIMC, DIMC);

    attn_h<<<dim3(NN / 128, NHEAD, BATCH), 256, ATT_SMEM_BYTES>>>();

    hgemm<<<dim3(DIMC / 128, BATCH * NN / 128), 256, G_SMEM>>>(
        5, 9, bp, 1.f, 0, -1, out, BATCH * NN, DIMC, DIMC);
}

// round 12
// speedup vs baseline: 1.1930x; 1.0226x over previous
#include <cuda_runtime.h>
#include <cuda_fp16.h>
#include <cstdint>

// ---------------------------------------------------------------------------
// Problem constants (B=4, H=W=64, DIM=512, 8 heads, SR=2)
// ---------------------------------------------------------------------------
#define BATCH   4
#define HH      64
#define WW      64
#define NN      (HH * WW)        // 4096
#define DIMC    512
#define NHEAD   8
#define HD      (DIMC / NHEAD)   // 64
#define SRR     2
#define HP      (HH / SRR)       // 32
#define WP      (WW / SRR)       // 32
#define NP      (HP * WP)        // 1024
#define KSR     (DIMC * SRR * SRR) // 2048

// ---------------------------------------------------------------------------
// Scratch (device globals)
// ---------------------------------------------------------------------------
__device__ __half g_xh  [(size_t)BATCH * NN * DIMC];
__device__ float  g_Xsr [(size_t)BATCH * NP * DIMC];
__device__ __half g_Xnh [(size_t)BATCH * NP * DIMC];
__device__ __half g_KVh [(size_t)BATCH * NP * 2 * DIMC];
__device__ __half g_Qh  [(size_t)BATCH * NN * DIMC];
__device__ __half g_Oh  [(size_t)BATCH * NN * DIMC];
__device__ __half g_Wsrh[(size_t)DIMC * KSR];            // (o, q*512+c)
__device__ __half g_Wkvh[(size_t)2 * DIMC * DIMC];
__device__ __half g_Wqh [(size_t)DIMC * DIMC];
__device__ __half g_Wph [(size_t)DIMC * DIMC];

__device__ __forceinline__ __half* pick_h(int id) {
    switch (id) {
        case 1: return g_xh;
        case 2: return g_Xnh;
        case 3: return g_KVh;
        case 4: return g_Qh;
        case 5: return g_Oh;
        case 6: return g_Wsrh;
        case 7: return g_Wkvh;
        case 8: return g_Wqh;
        case 9: return g_Wph;
    }
    return nullptr;
}

// ---------------------------------------------------------------------------
// PTX helpers
// ---------------------------------------------------------------------------
__device__ __forceinline__ uint32_t smem_u32(const void* p) {
    uint32_t a;
    asm("{ .reg .u64 t; cvta.to.shared.u64 t, %1; cvt.u32.u64 %0, t; }"
        : "=r"(a) : "l"(p));
    return a;
}
__device__ __forceinline__ uint32_t h2pack(float a, float b) {
    __half2 h = __floats2half2_rn(a, b);
    return *(uint32_t*)&h;
}
__device__ __forceinline__ void mma16816(float c[4],
                                         uint32_t a0, uint32_t a1,
                                         uint32_t a2, uint32_t a3,
                                         uint32_t b0, uint32_t b1) {
    asm volatile(
        "mma.sync.aligned.m16n8k16.row.col.f32.f16.f16.f32 "
        "{%0,%1,%2,%3}, {%4,%5,%6,%7}, {%8,%9}, {%0,%1,%2,%3};"
        : "+f"(c[0]), "+f"(c[1]), "+f"(c[2]), "+f"(c[3])
        : "r"(a0), "r"(a1), "r"(a2), "r"(a3), "r"(b0), "r"(b1));
}
__device__ __forceinline__ void ldmx4(uint32_t r[4], uint32_t addr) {
    asm volatile(
        "ldmatrix.sync.aligned.m8n8.x4.shared.b16 {%0,%1,%2,%3}, [%4];"
        : "=r"(r[0]), "=r"(r[1]), "=r"(r[2]), "=r"(r[3]) : "r"(addr));
}
__device__ __forceinline__ void ldmx4t(uint32_t r[4], uint32_t addr) {
    asm volatile(
        "ldmatrix.sync.aligned.m8n8.x4.trans.shared.b16 {%0,%1,%2,%3}, [%4];"
        : "=r"(r[0]), "=r"(r[1]), "=r"(r[2]), "=r"(r[3]) : "r"(addr));
}
#define CP_ASYNC16(saddr, gptr) \
    asm volatile("cp.async.cg.shared.global [%0], [%1], 16;" \
        :: "r"(saddr), "l"(gptr))
#define CP_COMMIT() asm volatile("cp.async.commit_group;" ::: "memory")
#define CP_WAIT(N)  asm volatile("cp.async.wait_group %0;" :: "n"(N) : "memory")

// ---------------------------------------------------------------------------
// prep: all fp32->fp16 converts + Wsr reorder in ONE launch
// ---------------------------------------------------------------------------
#define NX  (BATCH * NN * DIMC)          // 8388608
#define NKV (2 * DIMC * DIMC)            // 524288
#define NSQ (DIMC * DIMC)                // 262144
#define NVEC_ELE (NX + NKV + 2 * NSQ)    // 9437184
#define NVEC_BLK (NVEC_ELE / 4 / 256)    // 9216
#define NWSR_BLK (DIMC * KSR / 256)      // 4096

__global__ void __launch_bounds__(256) prep(
    const float* __restrict__ x,   const float* __restrict__ wkv,
    const float* __restrict__ wq,  const float* __restrict__ wp,
    const float* __restrict__ wsr)
{
    if (blockIdx.x < NVEC_BLK) {
        int e = (blockIdx.x * 256 + threadIdx.x) * 4;
        const float* src;
        __half* dst;
        if (e < NX)                 { src = x + e;                      dst = g_xh  + e; }
        else if (e < NX + NKV)      { src = wkv + (e - NX);             dst = g_Wkvh + (e - NX); }
        else if (e < NX + NKV + NSQ){ src = wq + (e - NX - NKV);        dst = g_Wqh + (e - NX - NKV); }
        else                        { src = wp + (e - NX - NKV - NSQ);  dst = g_Wph + (e - NX - NKV - NSQ); }
        float4 v = *(const float4*)src;
        *(uint2*)dst = make_uint2(h2pack(v.x, v.y), h2pack(v.z, v.w));
    } else {
        int idx = (blockIdx.x - NVEC_BLK) * 256 + threadIdx.x;
        int o = idx >> 11, rest = idx & 2047;
        int q = rest >> 9, c = rest & 511;
        g_Wsrh[idx] = __float2half(wsr[o * 2048 + c * 4 + q]);
    }
}

// ---------------------------------------------------------------------------
// hgemm body: 128x128 tile, BK=64, 3-stage cp.async ring, one sync per chunk,
// register-double-buffered fragments, immediate-offset ldmatrix addressing.
// ---------------------------------------------------------------------------
#define GST 72
#define GSTAGE (128 * GST * 2)           // 18432 bytes per operand stage
#define G_SMEM (3 * GSTAGE * 2)          // 110592
#define GMT (16 * GST * 2)               // 2304: 16-row stride in bytes

__device__ __forceinline__ void hgemm_body(
    char* smem_raw, int Aid, int patchA, int Wid,
    const float* bias, float scale,
    int Cfp16, int Cid, float* Cext,
    int M, int Nc, int K, int m0, int n0)
{
    const uint32_t As0 = smem_u32(smem_raw);
    const uint32_t Bs0 = As0 + 3 * GSTAGE;

    const __half* A = patchA ? g_xh : pick_h(Aid);
    const __half* W = pick_h(Wid);

    const int tid  = threadIdx.x;
    const int wid  = tid >> 5;
    const int lane = tid & 31;
    const int g = lane >> 2, t = lane & 3;
    const int wm = (wid & 3) * 32;
    const int wn = (wid >> 2) * 64;

    const int r0 = tid >> 2;             // 0..63
    const int cb = (tid & 3) * 16;       // 0,16,32,48 (halfs)
    int pb[2];
    if (patchA) {
#pragma unroll
        for (int j = 0; j < 2; j++) {
            int m = m0 + r0 + j * 64;
            int b = m >> 10, np = m & 1023;
            int i = np >> 5, jj = np & 31;
            pb[j] = (b << 12) + i * 128 + jj * 2;
        }
    }

    // lane-dependent fragment base offsets (bytes)
    const uint32_t abase = (uint32_t)((wm + (lane & 15)) * GST + ((lane >> 4) << 3)) * 2;
    const uint32_t bbase = (uint32_t)((wn + ((lane >> 4) << 3) + (lane & 7)) * GST) * 2
                         + ((lane >> 3) & 1) * 16;
    const uint32_t fillOff = (r0 * GST + cb) * 2;

    float acc[2][8][4];
#pragma unroll
    for (int mt = 0; mt < 2; mt++)
#pragma unroll
        for (int nt = 0; nt < 8; nt++)
#pragma unroll
            for (int c = 0; c < 4; c++) acc[mt][nt][c] = 0.f;

    const int nch = K >> 6;

    auto issue = [&](int kc, int buf) {
        const int k0 = kc << 6;
        const uint32_t aBase = As0 + buf * GSTAGE + fillOff;
        const uint32_t bBase = Bs0 + buf * GSTAGE + fillOff;
        if (patchA) {
            const int q = k0 >> 9;
            const int offq = ((q >> 1) << 6) + (q & 1);
            const int cc = (k0 & 511) + cb;
#pragma unroll
            for (int j = 0; j < 2; j++) {
                const __half* ap = A + (size_t)(pb[j] + offq) * DIMC + cc;
                const __half* wp = W + (size_t)(n0 + r0 + j * 64) * K + k0 + cb;
                CP_ASYNC16(aBase + j * 64 * GST * 2,      ap);
                CP_ASYNC16(aBase + j * 64 * GST * 2 + 16, ap + 8);
                CP_ASYNC16(bBase + j * 64 * GST * 2,      wp);
                CP_ASYNC16(bBase + j * 64 * GST * 2 + 16, wp + 8);
            }
        } else {
#pragma unroll
            for (int j = 0; j < 2; j++) {
                const __half* ap = A + (size_t)(m0 + r0 + j * 64) * K + k0 + cb;
                const __half* wp = W + (size_t)(n0 + r0 + j * 64) * K + k0 + cb;
                CP_ASYNC16(aBase + j * 64 * GST * 2,      ap);
                CP_ASYNC16(aBase + j * 64 * GST * 2 + 16, ap + 8);
                CP_ASYNC16(bBase + j * 64 * GST * 2,      wp);
                CP_ASYNC16(bBase + j * 64 * GST * 2 + 16, wp + 8);
            }
        }
        CP_COMMIT();
    };

    issue(0, 0);
    if (nch > 1) issue(1, 1);

    int buf = 0;
    for (int kc = 0; kc < nch; kc++) {
        const int rem = nch - 1 - kc;
        if (rem >= 1) CP_WAIT(1);
        else          CP_WAIT(0);
        __syncthreads();
        if (kc + 2 < nch) issue(kc + 2, (kc + 2) % 3);

        const uint32_t aS2 = As0 + buf * GSTAGE + abase;
        const uint32_t bS2 = Bs0 + buf * GSTAGE + bbase;

        uint32_t af[2][2][4], bf[2][4][4];
        ldmx4(af[0][0], aS2);
        ldmx4(af[0][1], aS2 + GMT);
#pragma unroll
        for (int bp = 0; bp < 4; bp++)
            ldmx4(bf[0][bp], bS2 + bp * GMT);

#pragma unroll
        for (int ks = 0; ks < 4; ks++) {
            const int cur = ks & 1;
            if (ks < 3) {
                const int nx = cur ^ 1;
                ldmx4(af[nx][0], aS2 + (ks + 1) * 32);
                ldmx4(af[nx][1], aS2 + GMT + (ks + 1) * 32);
#pragma unroll
                for (int bp = 0; bp < 4; bp++)
                    ldmx4(bf[nx][bp], bS2 + bp * GMT + (ks + 1) * 32);
            }
#pragma unroll
            for (int nt = 0; nt < 8; nt++) {
                uint32_t b0 = bf[cur][nt >> 1][(nt & 1) * 2];
                uint32_t b1 = bf[cur][nt >> 1][(nt & 1) * 2 + 1];
                mma16816(acc[0][nt], af[cur][0][0], af[cur][0][1],
                         af[cur][0][2], af[cur][0][3], b0, b1);
                mma16816(acc[1][nt], af[cur][1][0], af[cur][1][1],
                         af[cur][1][2], af[cur][1][3], b0, b1);
            }
        }
        buf = buf == 2 ? 0 : buf + 1;
    }

    // epilogue
    __half* Ch = Cfp16 ? pick_h(Cid) : nullptr;
    float*  Cf = Cfp16 ? nullptr : (Cext ? Cext : g_Xsr);
#pragma unroll
    for (int mt = 0; mt < 2; mt++) {
        const int mr = m0 + wm + mt * 16 + g;
#pragma unroll
        for (int nt = 0; nt < 8; nt++) {
            const int n = n0 + wn + nt * 8 + 2 * t;
            float bx = 0.f, by = 0.f;
            if (bias) { bx = bias[n]; by = bias[n + 1]; }
            float v00 = acc[mt][nt][0] * scale + bx;
            float v01 = acc[mt][nt][1] * scale + by;
            float v10 = acc[mt][nt][2] * scale + bx;
            float v11 = acc[mt][nt][3] * scale + by;
            if (Cfp16) {
                *(uint32_t*)&Ch[(size_t)mr * Nc + n]       = h2pack(v00, v01);
                *(uint32_t*)&Ch[(size_t)(mr + 8) * Nc + n] = h2pack(v10, v11);
            } else {
                *(float2*)&Cf[(size_t)mr * Nc + n]       = make_float2(v00, v01);
                *(float2*)&Cf[(size_t)(mr + 8) * Nc + n] = make_float2(v10, v11);
            }
        }
    }
}

__global__ void __launch_bounds__(256, 2) hgemm(
    int Aid, int Wid, const float* bias, float scale,
    int Cfp16, int Cid, float* Cext, int M, int Nc, int K)
{
    extern __shared__ char smem_raw[];
    hgemm_body(smem_raw, Aid, 0, Wid, bias, scale, Cfp16, Cid, Cext,
               M, Nc, K, blockIdx.y * 128, blockIdx.x * 128);
}

// fused: y<32 -> SR-conv (long jobs, scheduled FIRST), y>=32 -> Q-GEMM
__global__ void __launch_bounds__(256, 2) hgemm_qsr(const float* bsr)
{
    extern __shared__ char smem_raw[];
    if (blockIdx.y < 32) {
        hgemm_body(smem_raw, -1, 1, 6, bsr, 1.f, 0, -1, nullptr,
                   BATCH * NP, DIMC, KSR, blockIdx.y * 128, blockIdx.x * 128);
    } else {
        hgemm_body(smem_raw, 1, 0, 8, nullptr, 0.125f, 1, 4, nullptr,
                   BATCH * NN, DIMC, DIMC, (blockIdx.y - 32) * 128, blockIdx.x * 128);
    }
}

// ---------------------------------------------------------------------------
// LayerNorm: fp32 -> fp16
// ---------------------------------------------------------------------------
__global__ void __launch_bounds__(128) ln_rows(const float* __restrict__ gam,
                                               const float* __restrict__ bet)
{
    const float* p = g_Xsr + (size_t)blockIdx.x * DIMC;
    __half* o = g_Xnh + (size_t)blockIdx.x * DIMC;
    int tid = threadIdx.x;
    float4 v = *(const float4*)&p[tid * 4];
    float s  = v.x + v.y + v.z + v.w;
    float sq = v.x * v.x + v.y * v.y + v.z * v.z + v.w * v.w;
#pragma unroll
    for (int off = 16; off > 0; off >>= 1) {
        s  += __shfl_xor_sync(0xffffffffu, s,  off);
        sq += __shfl_xor_sync(0xffffffffu, sq, off);
    }
    __shared__ float ss[4], sqs[4];
    int wid = tid >> 5, lid = tid & 31;
    if (lid == 0) { ss[wid] = s; sqs[wid] = sq; }
    __syncthreads();
    s  = ss[0] + ss[1] + ss[2] + ss[3];
    sq = sqs[0] + sqs[1] + sqs[2] + sqs[3];
    float mu  = s * (1.f / DIMC);
    float var = sq * (1.f / DIMC) - mu * mu;
    float inv = rsqrtf(var + 1e-5f);
    int c = tid * 4;
    float4 gm = *(const float4*)&gam[c];
    float4 bt = *(const float4*)&bet[c];
    float r0 = (v.x - mu) * inv * gm.x + bt.x;
    float r1 = (v.y - mu) * inv * gm.y + bt.y;
    float r2 = (v.z - mu) * inv * gm.z + bt.z;
    float r3 = (v.w - mu) * inv * gm.w + bt.w;
    *(uint2*)&o[c] = make_uint2(h2pack(r0, r1), h2pack(r2, r3));
}

// ---------------------------------------------------------------------------
// Flash attention: fp16 mma, 4-stage K/V cp.async ring, one sync per tile,
// register-double-buffered K/V fragments, V-frag preload under softmax.
// ---------------------------------------------------------------------------
#define AST 72
#define AMT (16 * AST * 2)               // 2304
#define KVSTAGE (64 * AST * 2)           // 9216 bytes
#define ATT_SMEM_BYTES (128 * AST * 2 + 4 * KVSTAGE * 2)  // 92160

__global__ void __launch_bounds__(256, 2) attn_h()
{
    extern __shared__ __align__(16) __half smh[];
    __half* Qs = smh;
    const uint32_t Ks0 = smem_u32(smh + 128 * AST);
    const uint32_t Vs0 = Ks0 + 4 * KVSTAGE;

    const int tid  = threadIdx.x;
    const int wid  = tid >> 5;
    const int lane = tid & 31;
    const int g = lane >> 2, t = lane & 3;
    const int qb = blockIdx.x * 128;
    const int h  = blockIdx.y;
    const int b  = blockIdx.z;

    const __half* qbase = g_Qh + ((size_t)b * NN + qb) * DIMC + h * HD;
    const __half* kvb   = g_KVh + (size_t)b * NP * 2 * DIMC + h * HD;

#pragma unroll
    for (int j = 0; j < 4; j++) {
        int id = tid + j * 256;
        int r  = id >> 3;
        int c8 = (id & 7) * 8;
        CP_ASYNC16(smem_u32(&Qs[r * AST + c8]), qbase + (size_t)r * DIMC + c8);
    }
    CP_COMMIT();

    const int kr = tid >> 3;
    const int kc8 = (tid & 7) * 8;
    auto issue_kv = [&](int t0, int bufi) {
        const uint32_t kBase = Ks0 + bufi * KVSTAGE + (kr * AST + kc8) * 2;
        const uint32_t vBase = Vs0 + bufi * KVSTAGE + (kr * AST + kc8) * 2;
#pragma unroll
        for (int j = 0; j < 2; j++) {
            const __half* src = kvb + (size_t)(t0 + kr + j * 32) * (2 * DIMC) + kc8;
            CP_ASYNC16(kBase + j * 32 * AST * 2, src);
            CP_ASYNC16(vBase + j * 32 * AST * 2, src + DIMC);
        }
        CP_COMMIT();
    };

    issue_kv(0, 0);
    issue_kv(64, 1);
    issue_kv(128, 2);
    CP_WAIT(3);
    __syncthreads();

    const int wq = wid * 16;
    uint32_t qf[4][4];
#pragma unroll
    for (int ks = 0; ks < 4; ks++)
        ldmx4(qf[ks], smem_u32(&Qs[(wq + (lane & 15)) * AST
                                   + ks * 16 + ((lane >> 4) << 3)]));

    // lane-dependent K/V fragment base offsets (bytes, relative to stage base)
    const uint32_t kbase = (uint32_t)((((lane >> 4) << 3) + (lane & 7)) * AST) * 2
                         + ((lane >> 3) & 1) * 16;
    const uint32_t vbase = (uint32_t)((((lane >> 3) & 1) * 8 + (lane & 7)) * AST) * 2
                         + ((lane >> 4) << 3) * 2;

    float oacc[8][4];
#pragma unroll
    for (int dt = 0; dt < 8; dt++)
#pragma unroll
        for (int c = 0; c < 4; c++) oacc[dt][c] = 0.f;
    float m0r = -1e30f, m1r = -1e30f, l0r = 0.f, l1r = 0.f;

    const int niter = NP / 64;
    for (int it = 0; it < niter; it++) {
        const int rem = niter - 1 - it;
        if (rem >= 2)      CP_WAIT(2);
        else if (rem == 1) CP_WAIT(1);
        else               CP_WAIT(0);
        __syncthreads();
        if (it + 3 < niter) issue_kv((it + 3) * 64, (it + 3) & 3);

        const uint32_t Kb = Ks0 + (it & 3) * KVSTAGE + kbase;
        const uint32_t Vb = Vs0 + (it & 3) * KVSTAGE + vbase;

        // --- S = Q @ K^T with fragment double-buffering ---
        float sacc[8][4];
#pragma unroll
        for (int nt = 0; nt < 8; nt++)
#pragma unroll
            for (int c = 0; c < 4; c++) sacc[nt][c] = 0.f;

        uint32_t bfr[2][4][4];
#pragma unroll
        for (int bp = 0; bp < 4; bp++)
            ldmx4(bfr[0][bp], Kb + bp * AMT);
#pragma unroll
        for (int ks = 0; ks < 4; ks++) {
            const int cur = ks & 1;
            if (ks < 3) {
#pragma unroll
                for (int bp = 0; bp < 4; bp++)
                    ldmx4(bfr[cur ^ 1][bp], Kb + bp * AMT + (ks + 1) * 32);
            }
#pragma unroll
            for (int nt = 0; nt < 8; nt++)
                mma16816(sacc[nt], qf[ks][0], qf[ks][1], qf[ks][2], qf[ks][3],
                         bfr[cur][nt >> 1][(nt & 1) * 2],
                         bfr[cur][nt >> 1][(nt & 1) * 2 + 1]);
        }

        // preload V fragments for ks=0 (latency covered by softmax below)
        uint32_t vfr[2][4][4];
#pragma unroll
        for (int dp = 0; dp < 4; dp++)
            ldmx4t(vfr[0][dp], Vb + dp * 32);

        // --- online softmax ---
        float mn0 = m0r, mn1 = m1r;
#pragma unroll
        for (int nt = 0; nt < 8; nt++) {
            mn0 = fmaxf(mn0, fmaxf(sacc[nt][0], sacc[nt][1]));
            mn1 = fmaxf(mn1, fmaxf(sacc[nt][2], sacc[nt][3]));
        }
        mn0 = fmaxf(mn0, __shfl_xor_sync(0xffffffffu, mn0, 1));
        mn0 = fmaxf(mn0, __shfl_xor_sync(0xffffffffu, mn0, 2));
        mn1 = fmaxf(mn1, __shfl_xor_sync(0xffffffffu, mn1, 1));
        mn1 = fmaxf(mn1, __shfl_xor_sync(0xffffffffu, mn1, 2));
        float corr0 = __expf(m0r - mn0);
        float corr1 = __expf(m1r - mn1);
        m0r = mn0; m1r = mn1;
        l0r *= corr0; l1r *= corr1;
#pragma unroll
        for (int dt = 0; dt < 8; dt++) {
            oacc[dt][0] *= corr0; oacc[dt][1] *= corr0;
            oacc[dt][2] *= corr1; oacc[dt][3] *= corr1;
        }
        float ps0 = 0.f, ps1 = 0.f;
#pragma unroll
        for (int nt = 0; nt < 8; nt++) {
            sacc[nt][0] = __expf(sacc[nt][0] - mn0);
            sacc[nt][1] = __expf(sacc[nt][1] - mn0);
            sacc[nt][2] = __expf(sacc[nt][2] - mn1);
            sacc[nt][3] = __expf(sacc[nt][3] - mn1);
            ps0 += sacc[nt][0] + sacc[nt][1];
            ps1 += sacc[nt][2] + sacc[nt][3];
        }
        l0r += ps0; l1r += ps1;

        // --- pack P (C-layout == A-layout trick) ---
        uint32_t pk[4][4];
#pragma unroll
        for (int ks = 0; ks < 4; ks++) {
            pk[ks][0] = h2pack(sacc[2 * ks][0],     sacc[2 * ks][1]);
            pk[ks][1] = h2pack(sacc[2 * ks][2],     sacc[2 * ks][3]);
            pk[ks][2] = h2pack(sacc[2 * ks + 1][0], sacc[2 * ks + 1][1]);
            pk[ks][3] = h2pack(sacc[2 * ks + 1][2], sacc[2 * ks + 1][3]);
        }

        // --- O += P @ V with fragment double-buffering ---
#pragma unroll
        for (int ks = 0; ks < 4; ks++) {
            const int cur = ks & 1;
            if (ks < 3) {
#pragma unroll
                for (int dp = 0; dp < 4; dp++)
                    ldmx4t(vfr[cur ^ 1][dp], Vb + (ks + 1) * AMT + dp * 32);
            }
#pragma unroll
            for (int dt = 0; dt < 8; dt++)
                mma16816(oacc[dt], pk[ks][0], pk[ks][1], pk[ks][2], pk[ks][3],
                         vfr[cur][dt >> 1][(dt & 1) * 2],
                         vfr[cur][dt >> 1][(dt & 1) * 2 + 1]);
        }
    }

    l0r += __shfl_xor_sync(0xffffffffu, l0r, 1);
    l0r += __shfl_xor_sync(0xffffffffu, l0r, 2);
    l1r += __shfl_xor_sync(0xffffffffu, l1r, 1);
    l1r += __shfl_xor_sync(0xffffffffu, l1r, 2);
    const float inv0 = 1.f / l0r;
    const float inv1 = 1.f / l1r;

    const size_t orow0 = (size_t)b * NN + qb + wq + g;
#pragma unroll
    for (int dt = 0; dt < 8; dt++) {
        const int n = h * HD + dt * 8 + 2 * t;
        *(uint32_t*)&g_Oh[orow0 * DIMC + n] =
            h2pack(oacc[dt][0] * inv0, oacc[dt][1] * inv0);
        *(uint32_t*)&g_Oh[(orow0 + 8) * DIMC + n] =
            h2pack(oacc[dt][2] * inv1, oacc[dt][3] * inv1);
    }
}

// ---------------------------------------------------------------------------
// Launch
// ---------------------------------------------------------------------------
extern "C" void kernel_launch(void* const* d_in, const int* in_sizes, int n_in,
                              void* d_out, int out_size)
{
    const float* x    = (const float*)d_in[0];
    const float* Wq   = (const float*)d_in[3];
    const float* Wkv  = (const float*)d_in[4];
    const float* Wsr  = (const float*)d_in[5];
    const float* bsr  = (const float*)d_in[6];
    const float* ln_g = (const float*)d_in[7];
    const float* ln_b = (const float*)d_in[8];
    const float* Wp   = (const float*)d_in[9];
    const float* bp   = (const float*)d_in[10];
    float* out = (float*)d_out;

    cudaFuncSetAttribute(hgemm, cudaFuncAttributeMaxDynamicSharedMemorySize, G_SMEM);
    cudaFuncSetAttribute(hgemm_qsr, cudaFuncAttributeMaxDynamicSharedMemorySize, G_SMEM);
    cudaFuncSetAttribute(attn_h, cudaFuncAttributeMaxDynamicSharedMemorySize, ATT_SMEM_BYTES);

    // 0) all converts + reorder in one launch
    prep<<<NVEC_BLK + NWSR_BLK, 256>>>(x, Wkv, Wq, Wp, Wsr);

    // 1) fused: SR-conv (y<32, long) + Q-GEMM (y>=32, short)
    hgemm_qsr<<<dim3(DIMC / 128, 160), 256, G_SMEM>>>(bsr);

    // 2) LayerNorm -> fp16
    ln_rows<<<BATCH * NP, 128>>>(ln_g, ln_b);

    // 3) KV = Xn @ Wkv^T -> fp16
    hgemm<<<dim3(2 * DIMC / 128, BATCH * NP / 128), 256, G_SMEM>>>(
        2, 7, nullptr, 1.f, 1, 3, nullptr, BATCH * NP, 2 * DIMC, DIMC);

    // 4) attention
    attn_h<<<dim3(NN / 128, NHEAD, BATCH), 256, ATT_SMEM_BYTES>>>();

    // 5) out = O @ Wp^T + bp -> fp32
    hgemm<<<dim3(DIMC / 128, BATCH * NN / 128), 256, G_SMEM>>>(
        5, 9, bp, 1.f, 0, -1, out, BATCH * NN, DIMC, DIMC);
}

// round 14
// speedup vs baseline: 1.1995x; 1.0055x over previous
#include <cuda_runtime.h>
#include <cuda_fp16.h>
#include <cstdint>

// ---------------------------------------------------------------------------
// Problem constants (B=4, H=W=64, DIM=512, 8 heads, SR=2)
// ---------------------------------------------------------------------------
#define BATCH   4
#define HH      64
#define WW      64
#define NN      (HH * WW)        // 4096
#define DIMC    512
#define NHEAD   8
#define HD      (DIMC / NHEAD)   // 64
#define SRR     2
#define HP      (HH / SRR)       // 32
#define WP      (WW / SRR)       // 32
#define NP      (HP * WP)        // 1024
#define KSR     (DIMC * SRR * SRR) // 2048

// Q scale with log2(e) folded in: 0.125 * 1.4426950408889634
#define QSCALE  0.18033688011112043f

// ---------------------------------------------------------------------------
// Scratch (device globals)
// ---------------------------------------------------------------------------
__device__ __half g_xh  [(size_t)BATCH * NN * DIMC];
__device__ float  g_Xsr [(size_t)BATCH * NP * DIMC];
__device__ __half g_Xnh [(size_t)BATCH * NP * DIMC];
__device__ __half g_KVh [(size_t)BATCH * NP * 2 * DIMC];
__device__ __half g_Qh  [(size_t)BATCH * NN * DIMC];
__device__ __half g_Oh  [(size_t)BATCH * NN * DIMC];
__device__ __half g_Wsrh[(size_t)DIMC * KSR];            // (o, q*512+c)
__device__ __half g_Wkvh[(size_t)2 * DIMC * DIMC];
__device__ __half g_Wqh [(size_t)DIMC * DIMC];
__device__ __half g_Wph [(size_t)DIMC * DIMC];

__device__ __forceinline__ __half* pick_h(int id) {
    switch (id) {
        case 1: return g_xh;
        case 2: return g_Xnh;
        case 3: return g_KVh;
        case 4: return g_Qh;
        case 5: return g_Oh;
        case 6: return g_Wsrh;
        case 7: return g_Wkvh;
        case 8: return g_Wqh;
        case 9: return g_Wph;
    }
    return nullptr;
}

// ---------------------------------------------------------------------------
// PTX helpers
// ---------------------------------------------------------------------------
__device__ __forceinline__ uint32_t smem_u32(const void* p) {
    uint32_t a;
    asm("{ .reg .u64 t; cvta.to.shared.u64 t, %1; cvt.u32.u64 %0, t; }"
        : "=r"(a) : "l"(p));
    return a;
}
__device__ __forceinline__ uint32_t h2pack(float a, float b) {
    __half2 h = __floats2half2_rn(a, b);
    return *(uint32_t*)&h;
}
__device__ __forceinline__ float ex2f(float x) {
    float y;
    asm("ex2.approx.f32 %0, %1;" : "=f"(y) : "f"(x));
    return y;
}
__device__ __forceinline__ void mma16816(float c[4],
                                         uint32_t a0, uint32_t a1,
                                         uint32_t a2, uint32_t a3,
                                         uint32_t b0, uint32_t b1) {
    asm volatile(
        "mma.sync.aligned.m16n8k16.row.col.f32.f16.f16.f32 "
        "{%0,%1,%2,%3}, {%4,%5,%6,%7}, {%8,%9}, {%0,%1,%2,%3};"
        : "+f"(c[0]), "+f"(c[1]), "+f"(c[2]), "+f"(c[3])
        : "r"(a0), "r"(a1), "r"(a2), "r"(a3), "r"(b0), "r"(b1));
}
__device__ __forceinline__ void ldmx4(uint32_t r[4], uint32_t addr) {
    asm volatile(
        "ldmatrix.sync.aligned.m8n8.x4.shared.b16 {%0,%1,%2,%3}, [%4];"
        : "=r"(r[0]), "=r"(r[1]), "=r"(r[2]), "=r"(r[3]) : "r"(addr));
}
__device__ __forceinline__ void ldmx4t(uint32_t r[4], uint32_t addr) {
    asm volatile(
        "ldmatrix.sync.aligned.m8n8.x4.trans.shared.b16 {%0,%1,%2,%3}, [%4];"
        : "=r"(r[0]), "=r"(r[1]), "=r"(r[2]), "=r"(r[3]) : "r"(addr));
}
#define CP_ASYNC16(saddr, gptr) \
    asm volatile("cp.async.cg.shared.global [%0], [%1], 16;" \
        :: "r"(saddr), "l"(gptr))
#define CP_COMMIT() asm volatile("cp.async.commit_group;" ::: "memory")
#define CP_WAIT(N)  asm volatile("cp.async.wait_group %0;" :: "n"(N) : "memory")

// ---------------------------------------------------------------------------
// prep: all fp32->fp16 converts + Wsr reorder in ONE launch
// ---------------------------------------------------------------------------
#define NX  (BATCH * NN * DIMC)          // 8388608
#define NKV (2 * DIMC * DIMC)            // 524288
#define NSQ (DIMC * DIMC)                // 262144
#define NVEC_ELE (NX + NKV + 2 * NSQ)    // 9437184
#define NVEC_BLK (NVEC_ELE / 4 / 256)    // 9216
#define NWSR_BLK (DIMC * KSR / 256)      // 4096

__global__ void __launch_bounds__(256) prep(
    const float* __restrict__ x,   const float* __restrict__ wkv,
    const float* __restrict__ wq,  const float* __restrict__ wp,
    const float* __restrict__ wsr)
{
    if (blockIdx.x < NVEC_BLK) {
        int e = (blockIdx.x * 256 + threadIdx.x) * 4;
        const float* src;
        __half* dst;
        if (e < NX)                 { src = x + e;                      dst = g_xh  + e; }
        else if (e < NX + NKV)      { src = wkv + (e - NX);             dst = g_Wkvh + (e - NX); }
        else if (e < NX + NKV + NSQ){ src = wq + (e - NX - NKV);        dst = g_Wqh + (e - NX - NKV); }
        else                        { src = wp + (e - NX - NKV - NSQ);  dst = g_Wph + (e - NX - NKV - NSQ); }
        float4 v = *(const float4*)src;
        *(uint2*)dst = make_uint2(h2pack(v.x, v.y), h2pack(v.z, v.w));
    } else {
        int idx = (blockIdx.x - NVEC_BLK) * 256 + threadIdx.x;
        int o = idx >> 11, rest = idx & 2047;
        int q = rest >> 9, c = rest & 511;
        g_Wsrh[idx] = __float2half(wsr[o * 2048 + c * 4 + q]);
    }
}

// ---------------------------------------------------------------------------
// hgemm body: 128x128 tile, BK=64, 3-stage cp.async ring, one sync per chunk.
// A-fragments double-buffered; B-fragments single-buffered (reg budget).
// ---------------------------------------------------------------------------
#define GST 72
#define GSTAGE (128 * GST * 2)           // 18432 bytes per operand stage
#define G_SMEM (3 * GSTAGE * 2)          // 110592
#define GMT (16 * GST * 2)               // 2304: 16-row stride in bytes

__device__ __forceinline__ void hgemm_body(
    char* smem_raw, int Aid, int patchA, int Wid,
    const float* bias, float scale,
    int Cfp16, int Cid, float* Cext,
    int M, int Nc, int K, int m0, int n0)
{
    const uint32_t As0 = smem_u32(smem_raw);
    const uint32_t Bs0 = As0 + 3 * GSTAGE;

    const __half* A = patchA ? g_xh : pick_h(Aid);
    const __half* W = pick_h(Wid);

    const int tid  = threadIdx.x;
    const int wid  = tid >> 5;
    const int lane = tid & 31;
    const int g = lane >> 2, t = lane & 3;
    const int wm = (wid & 3) * 32;
    const int wn = (wid >> 2) * 64;

    const int r0 = tid >> 2;             // 0..63
    const int cb = (tid & 3) * 16;       // 0,16,32,48 (halfs)
    int pb[2];
    if (patchA) {
#pragma unroll
        for (int j = 0; j < 2; j++) {
            int m = m0 + r0 + j * 64;
            int b = m >> 10, np = m & 1023;
            int i = np >> 5, jj = np & 31;
            pb[j] = (b << 12) + i * 128 + jj * 2;
        }
    }

    // lane-dependent fragment base offsets (bytes)
    const uint32_t abase = (uint32_t)((wm + (lane & 15)) * GST + ((lane >> 4) << 3)) * 2;
    const uint32_t bbase = (uint32_t)((wn + ((lane >> 4) << 3) + (lane & 7)) * GST) * 2
                         + ((lane >> 3) & 1) * 16;
    const uint32_t fillOff = (r0 * GST + cb) * 2;

    float acc[2][8][4];
#pragma unroll
    for (int mt = 0; mt < 2; mt++)
#pragma unroll
        for (int nt = 0; nt < 8; nt++)
#pragma unroll
            for (int c = 0; c < 4; c++) acc[mt][nt][c] = 0.f;

    const int nch = K >> 6;

    auto issue = [&](int kc, int buf) {
        const int k0 = kc << 6;
        const uint32_t aBase = As0 + buf * GSTAGE + fillOff;
        const uint32_t bBase = Bs0 + buf * GSTAGE + fillOff;
        if (patchA) {
            const int q = k0 >> 9;
            const int offq = ((q >> 1) << 6) + (q & 1);
            const int cc = (k0 & 511) + cb;
#pragma unroll
            for (int j = 0; j < 2; j++) {
                const __half* ap = A + (size_t)(pb[j] + offq) * DIMC + cc;
                const __half* wp = W + (size_t)(n0 + r0 + j * 64) * K + k0 + cb;
                CP_ASYNC16(aBase + j * 64 * GST * 2,      ap);
                CP_ASYNC16(aBase + j * 64 * GST * 2 + 16, ap + 8);
                CP_ASYNC16(bBase + j * 64 * GST * 2,      wp);
                CP_ASYNC16(bBase + j * 64 * GST * 2 + 16, wp + 8);
            }
        } else {
#pragma unroll
            for (int j = 0; j < 2; j++) {
                const __half* ap = A + (size_t)(m0 + r0 + j * 64) * K + k0 + cb;
                const __half* wp = W + (size_t)(n0 + r0 + j * 64) * K + k0 + cb;
                CP_ASYNC16(aBase + j * 64 * GST * 2,      ap);
                CP_ASYNC16(aBase + j * 64 * GST * 2 + 16, ap + 8);
                CP_ASYNC16(bBase + j * 64 * GST * 2,      wp);
                CP_ASYNC16(bBase + j * 64 * GST * 2 + 16, wp + 8);
            }
        }
        CP_COMMIT();
    };

    issue(0, 0);
    if (nch > 1) issue(1, 1);

    int buf = 0;
    for (int kc = 0; kc < nch; kc++) {
        const int rem = nch - 1 - kc;
        if (rem >= 1) CP_WAIT(1);
        else          CP_WAIT(0);
        __syncthreads();
        if (kc + 2 < nch) issue(kc + 2, (kc + 2) % 3);

        const uint32_t aS2 = As0 + buf * GSTAGE + abase;
        const uint32_t bS2 = Bs0 + buf * GSTAGE + bbase;

        uint32_t af[2][2][4];            // A double-buffered
        ldmx4(af[0][0], aS2);
        ldmx4(af[0][1], aS2 + GMT);

#pragma unroll
        for (int ks = 0; ks < 4; ks++) {
            const int cur = ks & 1;
            uint32_t bf[4][4];           // B single-buffered
#pragma unroll
            for (int bp = 0; bp < 4; bp++)
                ldmx4(bf[bp], bS2 + bp * GMT + ks * 32);
            if (ks < 3) {
                const int nx = cur ^ 1;
                ldmx4(af[nx][0], aS2 + (ks + 1) * 32);
                ldmx4(af[nx][1], aS2 + GMT + (ks + 1) * 32);
            }
#pragma unroll
            for (int nt = 0; nt < 8; nt++) {
                uint32_t b0 = bf[nt >> 1][(nt & 1) * 2];
                uint32_t b1 = bf[nt >> 1][(nt & 1) * 2 + 1];
                mma16816(acc[0][nt], af[cur][0][0], af[cur][0][1],
                         af[cur][0][2], af[cur][0][3], b0, b1);
                mma16816(acc[1][nt], af[cur][1][0], af[cur][1][1],
                         af[cur][1][2], af[cur][1][3], b0, b1);
            }
        }
        buf = buf == 2 ? 0 : buf + 1;
    }

    // epilogue
    __half* Ch = Cfp16 ? pick_h(Cid) : nullptr;
    float*  Cf = Cfp16 ? nullptr : (Cext ? Cext : g_Xsr);
#pragma unroll
    for (int mt = 0; mt < 2; mt++) {
        const int mr = m0 + wm + mt * 16 + g;
#pragma unroll
        for (int nt = 0; nt < 8; nt++) {
            const int n = n0 + wn + nt * 8 + 2 * t;
            float bx = 0.f, by = 0.f;
            if (bias) { bx = bias[n]; by = bias[n + 1]; }
            float v00 = acc[mt][nt][0] * scale + bx;
            float v01 = acc[mt][nt][1] * scale + by;
            float v10 = acc[mt][nt][2] * scale + bx;
            float v11 = acc[mt][nt][3] * scale + by;
            if (Cfp16) {
                *(uint32_t*)&Ch[(size_t)mr * Nc + n]       = h2pack(v00, v01);
                *(uint32_t*)&Ch[(size_t)(mr + 8) * Nc + n] = h2pack(v10, v11);
            } else {
                *(float2*)&Cf[(size_t)mr * Nc + n]       = make_float2(v00, v01);
                *(float2*)&Cf[(size_t)(mr + 8) * Nc + n] = make_float2(v10, v11);
            }
        }
    }
}

__global__ void __launch_bounds__(256, 2) hgemm(
    int Aid, int Wid, const float* bias, float scale,
    int Cfp16, int Cid, float* Cext, int M, int Nc, int K)
{
    extern __shared__ char smem_raw[];
    hgemm_body(smem_raw, Aid, 0, Wid, bias, scale, Cfp16, Cid, Cext,
               M, Nc, K, blockIdx.y * 128, blockIdx.x * 128);
}

// fused: y<32 -> SR-conv (long jobs, scheduled FIRST), y>=32 -> Q-GEMM
__global__ void __launch_bounds__(256, 2) hgemm_qsr(const float* bsr)
{
    extern __shared__ char smem_raw[];
    if (blockIdx.y < 32) {
        hgemm_body(smem_raw, -1, 1, 6, bsr, 1.f, 0, -1, nullptr,
                   BATCH * NP, DIMC, KSR, blockIdx.y * 128, blockIdx.x * 128);
    } else {
        // Q scale carries log2(e) for exp2-domain softmax
        hgemm_body(smem_raw, 1, 0, 8, nullptr, QSCALE, 1, 4, nullptr,
                   BATCH * NN, DIMC, DIMC, (blockIdx.y - 32) * 128, blockIdx.x * 128);
    }
}

// ---------------------------------------------------------------------------
// LayerNorm: fp32 -> fp16
// ---------------------------------------------------------------------------
__global__ void __launch_bounds__(128) ln_rows(const float* __restrict__ gam,
                                               const float* __restrict__ bet)
{
    const float* p = g_Xsr + (size_t)blockIdx.x * DIMC;
    __half* o = g_Xnh + (size_t)blockIdx.x * DIMC;
    int tid = threadIdx.x;
    float4 v = *(const float4*)&p[tid * 4];
    float s  = v.x + v.y + v.z + v.w;
    float sq = v.x * v.x + v.y * v.y + v.z * v.z + v.w * v.w;
#pragma unroll
    for (int off = 16; off > 0; off >>= 1) {
        s  += __shfl_xor_sync(0xffffffffu, s,  off);
        sq += __shfl_xor_sync(0xffffffffu, sq, off);
    }
    __shared__ float ss[4], sqs[4];
    int wid = tid >> 5, lid = tid & 31;
    if (lid == 0) { ss[wid] = s; sqs[wid] = sq; }
    __syncthreads();
    s  = ss[0] + ss[1] + ss[2] + ss[3];
    sq = sqs[0] + sqs[1] + sqs[2] + sqs[3];
    float mu  = s * (1.f / DIMC);
    float var = sq * (1.f / DIMC) - mu * mu;
    float inv = rsqrtf(var + 1e-5f);
    int c = tid * 4;
    float4 gm = *(const float4*)&gam[c];
    float4 bt = *(const float4*)&bet[c];
    float r0 = (v.x - mu) * inv * gm.x + bt.x;
    float r1 = (v.y - mu) * inv * gm.y + bt.y;
    float r2 = (v.z - mu) * inv * gm.z + bt.z;
    float r3 = (v.w - mu) * inv * gm.w + bt.w;
    *(uint2*)&o[c] = make_uint2(h2pack(r0, r1), h2pack(r2, r3));
}

// ---------------------------------------------------------------------------
// Flash attention: fp16 mma, 4-stage K/V cp.async ring, one sync per tile,
// exp2-domain softmax, single-buffered fragments (no spills), V preload.
// ---------------------------------------------------------------------------
#define AST 72
#define AMT (16 * AST * 2)               // 2304
#define KVSTAGE (64 * AST * 2)           // 9216 bytes
#define ATT_SMEM_BYTES (128 * AST * 2 + 4 * KVSTAGE * 2)  // 92160

__global__ void __launch_bounds__(256, 2) attn_h()
{
    extern __shared__ __align__(16) __half smh[];
    __half* Qs = smh;
    const uint32_t Ks0 = smem_u32(smh + 128 * AST);
    const uint32_t Vs0 = Ks0 + 4 * KVSTAGE;

    const int tid  = threadIdx.x;
    const int wid  = tid >> 5;
    const int lane = tid & 31;
    const int g = lane >> 2, t = lane & 3;
    const int qb = blockIdx.x * 128;
    const int h  = blockIdx.y;
    const int b  = blockIdx.z;

    const __half* qbase = g_Qh + ((size_t)b * NN + qb) * DIMC + h * HD;
    const __half* kvb   = g_KVh + (size_t)b * NP * 2 * DIMC + h * HD;

#pragma unroll
    for (int j = 0; j < 4; j++) {
        int id = tid + j * 256;
        int r  = id >> 3;
        int c8 = (id & 7) * 8;
        CP_ASYNC16(smem_u32(&Qs[r * AST + c8]), qbase + (size_t)r * DIMC + c8);
    }
    CP_COMMIT();

    const int kr = tid >> 3;
    const int kc8 = (tid & 7) * 8;
    auto issue_kv = [&](int t0, int bufi) {
        const uint32_t kBase = Ks0 + bufi * KVSTAGE + (kr * AST + kc8) * 2;
        const uint32_t vBase = Vs0 + bufi * KVSTAGE + (kr * AST + kc8) * 2;
#pragma unroll
        for (int j = 0; j < 2; j++) {
            const __half* src = kvb + (size_t)(t0 + kr + j * 32) * (2 * DIMC) + kc8;
            CP_ASYNC16(kBase + j * 32 * AST * 2, src);
            CP_ASYNC16(vBase + j * 32 * AST * 2, src + DIMC);
        }
        CP_COMMIT();
    };

    issue_kv(0, 0);
    issue_kv(64, 1);
    issue_kv(128, 2);
    CP_WAIT(3);
    __syncthreads();

    const int wq = wid * 16;
    uint32_t qf[4][4];
#pragma unroll
    for (int ks = 0; ks < 4; ks++)
        ldmx4(qf[ks], smem_u32(&Qs[(wq + (lane & 15)) * AST
                                   + ks * 16 + ((lane >> 4) << 3)]));

    // lane-dependent K/V fragment base offsets (bytes, relative to stage base)
    const uint32_t kbase = (uint32_t)((((lane >> 4) << 3) + (lane & 7)) * AST) * 2
                         + ((lane >> 3) & 1) * 16;
    const uint32_t vbase = (uint32_t)((((lane >> 3) & 1) * 8 + (lane & 7)) * AST) * 2
                         + ((lane >> 4) << 3) * 2;

    float oacc[8][4];
#pragma unroll
    for (int dt = 0; dt < 8; dt++)
#pragma unroll
        for (int c = 0; c < 4; c++) oacc[dt][c] = 0.f;
    float m0r = -1e30f, m1r = -1e30f, l0r = 0.f, l1r = 0.f;

    const int niter = NP / 64;
    for (int it = 0; it < niter; it++) {
        const int rem = niter - 1 - it;
        if (rem >= 2)      CP_WAIT(2);
        else if (rem == 1) CP_WAIT(1);
        else               CP_WAIT(0);
        __syncthreads();
        if (it + 3 < niter) issue_kv((it + 3) * 64, (it + 3) & 3);

        const uint32_t Kb = Ks0 + (it & 3) * KVSTAGE + kbase;
        const uint32_t Vb = Vs0 + (it & 3) * KVSTAGE + vbase;

        // --- S = Q @ K^T (K frags single-buffered) ---
        float sacc[8][4];
#pragma unroll
        for (int nt = 0; nt < 8; nt++)
#pragma unroll
            for (int c = 0; c < 4; c++) sacc[nt][c] = 0.f;

#pragma unroll
        for (int ks = 0; ks < 4; ks++) {
            uint32_t bfr[4][4];
#pragma unroll
            for (int bp = 0; bp < 4; bp++)
                ldmx4(bfr[bp], Kb + bp * AMT + ks * 32);
#pragma unroll
            for (int nt = 0; nt < 8; nt++)
                mma16816(sacc[nt], qf[ks][0], qf[ks][1], qf[ks][2], qf[ks][3],
                         bfr[nt >> 1][(nt & 1) * 2],
                         bfr[nt >> 1][(nt & 1) * 2 + 1]);
        }

        // preload V fragments for ks=0 (latency covered by softmax below)
        uint32_t vfr[4][4];
#pragma unroll
        for (int dp = 0; dp < 4; dp++)
            ldmx4t(vfr[dp], Vb + dp * 32);

        // --- online softmax (log2 domain; scores pre-scaled by log2e) ---
        float mn0 = m0r, mn1 = m1r;
#pragma unroll
        for (int nt = 0; nt < 8; nt++) {
            mn0 = fmaxf(mn0, fmaxf(sacc[nt][0], sacc[nt][1]));
            mn1 = fmaxf(mn1, fmaxf(sacc[nt][2], sacc[nt][3]));
        }
        mn0 = fmaxf(mn0, __shfl_xor_sync(0xffffffffu, mn0, 1));
        mn0 = fmaxf(mn0, __shfl_xor_sync(0xffffffffu, mn0, 2));
        mn1 = fmaxf(mn1, __shfl_xor_sync(0xffffffffu, mn1, 1));
        mn1 = fmaxf(mn1, __shfl_xor_sync(0xffffffffu, mn1, 2));
        float corr0 = ex2f(m0r - mn0);
        float corr1 = ex2f(m1r - mn1);
        m0r = mn0; m1r = mn1;
        l0r *= corr0; l1r *= corr1;
#pragma unroll
        for (int dt = 0; dt < 8; dt++) {
            oacc[dt][0] *= corr0; oacc[dt][1] *= corr0;
            oacc[dt][2] *= corr1; oacc[dt][3] *= corr1;
        }
        float ps0 = 0.f, ps1 = 0.f;
#pragma unroll
        for (int nt = 0; nt < 8; nt++) {
            sacc[nt][0] = ex2f(sacc[nt][0] - mn0);
            sacc[nt][1] = ex2f(sacc[nt][1] - mn0);
            sacc[nt][2] = ex2f(sacc[nt][2] - mn1);
            sacc[nt][3] = ex2f(sacc[nt][3] - mn1);
            ps0 += sacc[nt][0] + sacc[nt][1];
            ps1 += sacc[nt][2] + sacc[nt][3];
        }
        l0r += ps0; l1r += ps1;

        // --- pack P (C-layout == A-layout trick) ---
        uint32_t pk[4][4];
#pragma unroll
        for (int ks = 0; ks < 4; ks++) {
            pk[ks][0] = h2pack(sacc[2 * ks][0],     sacc[2 * ks][1]);
            pk[ks][1] = h2pack(sacc[2 * ks][2],     sacc[2 * ks][3]);
            pk[ks][2] = h2pack(sacc[2 * ks + 1][0], sacc[2 * ks + 1][1]);
            pk[ks][3] = h2pack(sacc[2 * ks + 1][2], sacc[2 * ks + 1][3]);
        }

        // --- O += P @ V (V frags single-buffered; next load after use) ---
#pragma unroll
        for (int ks = 0; ks < 4; ks++) {
#pragma unroll
            for (int dt = 0; dt < 8; dt++)
                mma16816(oacc[dt], pk[ks][0], pk[ks][1], pk[ks][2], pk[ks][3],
                         vfr[dt >> 1][(dt & 1) * 2],
                         vfr[dt >> 1][(dt & 1) * 2 + 1]);
            if (ks < 3) {
#pragma unroll
                for (int dp = 0; dp < 4; dp++)
                    ldmx4t(vfr[dp], Vb + (ks + 1) * AMT + dp * 32);
            }
        }
    }

    l0r += __shfl_xor_sync(0xffffffffu, l0r, 1);
    l0r += __shfl_xor_sync(0xffffffffu, l0r, 2);
    l1r += __shfl_xor_sync(0xffffffffu, l1r, 1);
    l1r += __shfl_xor_sync(0xffffffffu, l1r, 2);
    const float inv0 = 1.f / l0r;
    const float inv1 = 1.f / l1r;

    const size_t orow0 = (size_t)b * NN + qb + wq + g;
#pragma unroll
    for (int dt = 0; dt < 8; dt++) {
        const int n = h * HD + dt * 8 + 2 * t;
        *(uint32_t*)&g_Oh[orow0 * DIMC + n] =
            h2pack(oacc[dt][0] * inv0, oacc[dt][1] * inv0);
        *(uint32_t*)&g_Oh[(orow0 + 8) * DIMC + n] =
            h2pack(oacc[dt][2] * inv1, oacc[dt][3] * inv1);
    }
}

// ---------------------------------------------------------------------------
// Launch
// ---------------------------------------------------------------------------
extern "C" void kernel_launch(void* const* d_in, const int* in_sizes, int n_in,
                              void* d_out, int out_size)
{
    const float* x    = (const float*)d_in[0];
    const float* Wq   = (const float*)d_in[3];
    const float* Wkv  = (const float*)d_in[4];
    const float* Wsr  = (const float*)d_in[5];
    const float* bsr  = (const float*)d_in[6];
    const float* ln_g = (const float*)d_in[7];
    const float* ln_b = (const float*)d_in[8];
    const float* Wp   = (const float*)d_in[9];
    const float* bp   = (const float*)d_in[10];
    float* out = (float*)d_out;

    cudaFuncSetAttribute(hgemm, cudaFuncAttributeMaxDynamicSharedMemorySize, G_SMEM);
    cudaFuncSetAttribute(hgemm_qsr, cudaFuncAttributeMaxDynamicSharedMemorySize, G_SMEM);
    cudaFuncSetAttribute(attn_h, cudaFuncAttributeMaxDynamicSharedMemorySize, ATT_SMEM_BYTES);

    // 0) all converts + reorder in one launch
    prep<<<NVEC_BLK + NWSR_BLK, 256>>>(x, Wkv, Wq, Wp, Wsr);

    // 1) fused: SR-conv (y<32, long) + Q-GEMM (y>=32, short)
    hgemm_qsr<<<dim3(DIMC / 128, 160), 256, G_SMEM>>>(bsr);

    // 2) LayerNorm -> fp16
    ln_rows<<<BATCH * NP, 128>>>(ln_g, ln_b);

    // 3) KV = Xn @ Wkv^T -> fp16
    hgemm<<<dim3(2 * DIMC / 128, BATCH * NP / 128), 256, G_SMEM>>>(
        2, 7, nullptr, 1.f, 1, 3, nullptr, BATCH * NP, 2 * DIMC, DIMC);

    // 4) attention (exp2-domain softmax)
    attn_h<<<dim3(NN / 128, NHEAD, BATCH), 256, ATT_SMEM_BYTES>>>();

    // 5) out = O @ Wp^T + bp -> fp32
    hgemm<<<dim3(DIMC / 128, BATCH * NN / 128), 256, G_SMEM>>>(
        5, 9, bp, 1.f, 0, -1, out, BATCH * NN, DIMC, DIMC);
}